// round 4
// baseline (speedup 1.0000x reference)
#include <cuda_runtime.h>
#include <math.h>

// Problem constants
#define BATCH 4
#define SEQ   4096
#define DIM   1024
#define MTOT  (BATCH * SEQ)     // 16384
#define HALF_D (DIM / 2)        // 512

// GEMM tiling
#define BM 128
#define BN 128
#define BK 8
#define TM 8
#define TN 8
#define NTHREADS 256

// -------- device scratch (no cudaMalloc allowed) --------
__device__ float g_Q[(size_t)MTOT * DIM];
__device__ float g_K[(size_t)MTOT * DIM];
__device__ float g_V[(size_t)MTOT * DIM];
__device__ float g_P[(size_t)BATCH * SEQ * SEQ];   // 256 MB scores/probs
__device__ float g_cos[(size_t)SEQ * HALF_D];
__device__ float g_sin[(size_t)SEQ * HALF_D];

// ============================================================
// RoPE cos/sin table, computed in double for accuracy
// ============================================================
__global__ void trig_table_kernel(float* ct, float* st) {
    int idx = blockIdx.x * blockDim.x + threadIdx.x;
    if (idx >= SEQ * HALF_D) return;
    int s = idx / HALF_D;
    int j = idx % HALF_D;
    // inv_freq = 10000 ^ (-(2j)/D) = exp(-(2j/D) * ln(10000))
    double inv = exp(-((double)(2 * j) / (double)DIM) * 9.210340371976184);
    double ang = (double)s * inv;
    double sv, cv;
    sincos(ang, &sv, &cv);
    ct[idx] = (float)cv;
    st[idx] = (float)sv;
}

// ============================================================
// Apply RoPE in place to Q and K
// ============================================================
__global__ void rope_apply_kernel(float* __restrict__ Q, float* __restrict__ K,
                                  const float* __restrict__ ct,
                                  const float* __restrict__ st) {
    int idx = blockIdx.x * blockDim.x + threadIdx.x;   // pair index
    if (idx >= MTOT * HALF_D) return;
    int row = idx / HALF_D;
    int j   = idx % HALF_D;
    int s   = row & (SEQ - 1);
    float c  = ct[(size_t)s * HALF_D + j];
    float sn = st[(size_t)s * HALF_D + j];

    float2* Q2 = (float2*)Q;
    float2* K2 = (float2*)K;
    size_t p = (size_t)row * HALF_D + j;

    float2 q = Q2[p];
    float2 r;
    r.x = q.x * c - q.y * sn;
    r.y = q.x * sn + q.y * c;
    Q2[p] = r;

    float2 k = K2[p];
    float2 rk;
    rk.x = k.x * c - k.y * sn;
    rk.y = k.x * sn + k.y * c;
    K2[p] = rk;
}

// ============================================================
// NT SGEMM: C[M,N] = A[M,K] * B[N,K]^T   (both K-major, K=1024)
// Used for Q/K/V projections. grid = (N/BN, M/BM), 256 threads.
// ============================================================
__global__ __launch_bounds__(NTHREADS)
void qkv_gemm_kernel(const float* __restrict__ A, const float* __restrict__ Bm,
                     float* __restrict__ C) {
    __shared__ float As[BK][BM];
    __shared__ float Bs[BK][BN];

    const int n0 = blockIdx.x * BN;
    const int m0 = blockIdx.y * BM;
    const int tid = threadIdx.x;
    const int tx = tid % 16;
    const int ty = tid / 16;

    const int lrow = tid >> 1;         // 0..127
    const int lcol = (tid & 1) * 4;    // 0 or 4

    const float* Aptr = A + (size_t)(m0 + lrow) * DIM + lcol;
    const float* Bptr = Bm + (size_t)(n0 + lrow) * DIM + lcol;

    float acc[TM][TN];
#pragma unroll
    for (int i = 0; i < TM; i++)
#pragma unroll
        for (int j = 0; j < TN; j++) acc[i][j] = 0.0f;

    for (int k0 = 0; k0 < DIM; k0 += BK) {
        float4 av = *(const float4*)(Aptr + k0);
        float4 bv = *(const float4*)(Bptr + k0);
        __syncthreads();
        As[lcol + 0][lrow] = av.x; As[lcol + 1][lrow] = av.y;
        As[lcol + 2][lrow] = av.z; As[lcol + 3][lrow] = av.w;
        Bs[lcol + 0][lrow] = bv.x; Bs[lcol + 1][lrow] = bv.y;
        Bs[lcol + 2][lrow] = bv.z; Bs[lcol + 3][lrow] = bv.w;
        __syncthreads();
#pragma unroll
        for (int kk = 0; kk < BK; kk++) {
            float a[TM], b[TN];
#pragma unroll
            for (int i = 0; i < TM; i++) a[i] = As[kk][ty * TM + i];
#pragma unroll
            for (int j = 0; j < TN; j++) b[j] = Bs[kk][tx * TN + j];
#pragma unroll
            for (int i = 0; i < TM; i++)
#pragma unroll
                for (int j = 0; j < TN; j++) acc[i][j] = fmaf(a[i], b[j], acc[i][j]);
        }
    }

#pragma unroll
    for (int i = 0; i < TM; i++) {
        size_t base = (size_t)(m0 + ty * TM + i) * DIM + n0 + tx * TN;
#pragma unroll
        for (int j = 0; j < TN; j++) C[base + j] = acc[i][j];
    }
}

// ============================================================
// Scores: per batch, P = Q_b * K_b^T * (1/32), lower-triangle tiles only.
// grid = (SEQ/BN, SEQ/BM, BATCH)
// ============================================================
__global__ __launch_bounds__(NTHREADS)
void scores_kernel(const float* __restrict__ Qg, const float* __restrict__ Kg,
                   float* __restrict__ P) {
    const int n0 = blockIdx.x * BN;
    const int m0 = blockIdx.y * BM;
    if (n0 > m0) return;   // tile fully above causal diagonal
    const int b = blockIdx.z;

    const float* A  = Qg + (size_t)b * SEQ * DIM;
    const float* Bm = Kg + (size_t)b * SEQ * DIM;

    __shared__ float As[BK][BM];
    __shared__ float Bs[BK][BN];

    const int tid = threadIdx.x;
    const int tx = tid % 16;
    const int ty = tid / 16;
    const int lrow = tid >> 1;
    const int lcol = (tid & 1) * 4;

    const float* Aptr = A + (size_t)(m0 + lrow) * DIM + lcol;
    const float* Bptr = Bm + (size_t)(n0 + lrow) * DIM + lcol;

    float acc[TM][TN];
#pragma unroll
    for (int i = 0; i < TM; i++)
#pragma unroll
        for (int j = 0; j < TN; j++) acc[i][j] = 0.0f;

    for (int k0 = 0; k0 < DIM; k0 += BK) {
        float4 av = *(const float4*)(Aptr + k0);
        float4 bv = *(const float4*)(Bptr + k0);
        __syncthreads();
        As[lcol + 0][lrow] = av.x; As[lcol + 1][lrow] = av.y;
        As[lcol + 2][lrow] = av.z; As[lcol + 3][lrow] = av.w;
        Bs[lcol + 0][lrow] = bv.x; Bs[lcol + 1][lrow] = bv.y;
        Bs[lcol + 2][lrow] = bv.z; Bs[lcol + 3][lrow] = bv.w;
        __syncthreads();
#pragma unroll
        for (int kk = 0; kk < BK; kk++) {
            float a[TM], b2[TN];
#pragma unroll
            for (int i = 0; i < TM; i++) a[i] = As[kk][ty * TM + i];
#pragma unroll
            for (int j = 0; j < TN; j++) b2[j] = Bs[kk][tx * TN + j];
#pragma unroll
            for (int i = 0; i < TM; i++)
#pragma unroll
                for (int j = 0; j < TN; j++) acc[i][j] = fmaf(a[i], b2[j], acc[i][j]);
        }
    }

    const float scale = 1.0f / 32.0f;   // 1/sqrt(1024)
    float* Pb = P + (size_t)b * SEQ * SEQ;
#pragma unroll
    for (int i = 0; i < TM; i++) {
        size_t base = (size_t)(m0 + ty * TM + i) * SEQ + n0 + tx * TN;
#pragma unroll
        for (int j = 0; j < TN; j++) Pb[base + j] = acc[i][j] * scale;
    }
}

// ============================================================
// Causal row softmax, in place. One block per row. Zero-pads
// columns (i, round_up(i+1,128)) so PV can run dense k-tiles.
// ============================================================
__global__ __launch_bounds__(NTHREADS)
void softmax_kernel(float* __restrict__ P) {
    __shared__ float red[NTHREADS];
    const int rowg = blockIdx.x;
    const int b = rowg >> 12;        // / 4096
    const int i = rowg & (SEQ - 1);
    float* p = P + (size_t)b * SEQ * SEQ + (size_t)i * SEQ;
    const int L = i + 1;
    const int tid = threadIdx.x;

    float m = -3.0e38f;
    for (int j = tid; j < L; j += NTHREADS) m = fmaxf(m, p[j]);
    red[tid] = m; __syncthreads();
    for (int s2 = NTHREADS / 2; s2 > 0; s2 >>= 1) {
        if (tid < s2) red[tid] = fmaxf(red[tid], red[tid + s2]);
        __syncthreads();
    }
    m = red[0]; __syncthreads();

    float sum = 0.0f;
    for (int j = tid; j < L; j += NTHREADS) {
        float e = expf(p[j] - m);
        p[j] = e;
        sum += e;
    }
    red[tid] = sum; __syncthreads();
    for (int s2 = NTHREADS / 2; s2 > 0; s2 >>= 1) {
        if (tid < s2) red[tid] += red[tid + s2];
        __syncthreads();
    }
    const float inv = 1.0f / red[0];
    for (int j = tid; j < L; j += NTHREADS) p[j] *= inv;

    const int bound = (i & ~127) + 128;    // round_up(i+1, 128)
    for (int j = L + tid; j < bound; j += NTHREADS) p[j] = 0.0f;
}

// ============================================================
// PV NN SGEMM: O_b = P_b[SEQ,SEQ] * V_b[SEQ,DIM], k truncated at
// the diagonal tile boundary. grid = (DIM/BN, SEQ/BM, BATCH)
// ============================================================
__global__ __launch_bounds__(NTHREADS)
void pv_kernel(const float* __restrict__ Pg, const float* __restrict__ Vg,
               float* __restrict__ O) {
    const int n0 = blockIdx.x * BN;
    const int m0 = blockIdx.y * BM;
    const int b  = blockIdx.z;

    const float* A  = Pg + (size_t)b * SEQ * SEQ;   // lda = SEQ
    const float* Bm = Vg + (size_t)b * SEQ * DIM;   // ldb = DIM

    __shared__ float As[BK][BM];
    __shared__ float Bs[BK][BN];

    const int tid = threadIdx.x;
    const int tx = tid % 16;
    const int ty = tid / 16;

    const int arow = tid >> 1;
    const int acol = (tid & 1) * 4;
    const int brow = tid >> 5;          // 0..7
    const int bcol = (tid & 31) * 4;    // 0..124

    const float* Aptr = A + (size_t)(m0 + arow) * SEQ + acol;
    const float* Bptr = Bm + (size_t)brow * DIM + n0 + bcol;

    float acc[TM][TN];
#pragma unroll
    for (int i = 0; i < TM; i++)
#pragma unroll
        for (int j = 0; j < TN; j++) acc[i][j] = 0.0f;

    const int kEnd = m0 + BM;   // causal: columns >= m0+128 are zero/unneeded
    for (int k0 = 0; k0 < kEnd; k0 += BK) {
        float4 av = *(const float4*)(Aptr + k0);
        float4 bv = *(const float4*)(Bptr + (size_t)k0 * DIM);
        __syncthreads();
        As[acol + 0][arow] = av.x; As[acol + 1][arow] = av.y;
        As[acol + 2][arow] = av.z; As[acol + 3][arow] = av.w;
        *(float4*)&Bs[brow][bcol] = bv;
        __syncthreads();
#pragma unroll
        for (int kk = 0; kk < BK; kk++) {
            float a[TM], b2[TN];
#pragma unroll
            for (int i = 0; i < TM; i++) a[i] = As[kk][ty * TM + i];
#pragma unroll
            for (int j = 0; j < TN; j++) b2[j] = Bs[kk][tx * TN + j];
#pragma unroll
            for (int i = 0; i < TM; i++)
#pragma unroll
                for (int j = 0; j < TN; j++) acc[i][j] = fmaf(a[i], b2[j], acc[i][j]);
        }
    }

#pragma unroll
    for (int i = 0; i < TM; i++) {
        size_t base = (size_t)b * SEQ * DIM + (size_t)(m0 + ty * TM + i) * DIM + n0 + tx * TN;
#pragma unroll
        for (int j = 0; j < TN; j++) O[base + j] = acc[i][j];
    }
}

// ============================================================
// Launch
// ============================================================
extern "C" void kernel_launch(void* const* d_in, const int* in_sizes, int n_in,
                              void* d_out, int out_size) {
    const float* x  = (const float*)d_in[0];
    const float* Wq = (const float*)d_in[1];
    const float* Wk = (const float*)d_in[2];
    const float* Wv = (const float*)d_in[3];
    float* out = (float*)d_out;

    float *Qp, *Kp, *Vp, *Pp, *Cp, *Sp;
    cudaGetSymbolAddress((void**)&Qp, g_Q);
    cudaGetSymbolAddress((void**)&Kp, g_K);
    cudaGetSymbolAddress((void**)&Vp, g_V);
    cudaGetSymbolAddress((void**)&Pp, g_P);
    cudaGetSymbolAddress((void**)&Cp, g_cos);
    cudaGetSymbolAddress((void**)&Sp, g_sin);

    // 1) RoPE trig tables
    {
        int total = SEQ * HALF_D;
        trig_table_kernel<<<(total + 255) / 256, 256>>>(Cp, Sp);
    }

    // 2) Q, K, V projections
    {
        dim3 grid(DIM / BN, MTOT / BM);   // (8, 128)
        qkv_gemm_kernel<<<grid, NTHREADS>>>(x, Wq, Qp);
        qkv_gemm_kernel<<<grid, NTHREADS>>>(x, Wk, Kp);
        qkv_gemm_kernel<<<grid, NTHREADS>>>(x, Wv, Vp);
    }

    // 3) RoPE on Q and K
    {
        int total = MTOT * HALF_D;
        rope_apply_kernel<<<(total + 255) / 256, 256>>>(Qp, Kp, Cp, Sp);
    }

    // 4) Causal scores
    {
        dim3 grid(SEQ / BN, SEQ / BM, BATCH);   // (32, 32, 4)
        scores_kernel<<<grid, NTHREADS>>>(Qp, Kp, Pp);
    }

    // 5) Softmax
    softmax_kernel<<<BATCH * SEQ, NTHREADS>>>(Pp);

    // 6) O = P @ V
    {
        dim3 grid(DIM / BN, SEQ / BM, BATCH);   // (8, 32, 4)
        pv_kernel<<<grid, NTHREADS>>>(Pp, Vp, out);
    }
}

// round 5
// speedup vs baseline: 1.4004x; 1.4004x over previous
#include <cuda_runtime.h>
#include <math.h>
#include <stdint.h>

// Problem constants
#define BATCH 4
#define SEQ   4096
#define DIM   1024
#define MTOT  (BATCH * SEQ)     // 16384
#define HALF_D (DIM / 2)        // 512

// GEMM tiling
#define BM 128
#define BN 128
#define BK 32
#define NTHREADS 256
#define SKA 36                          // padded smem row stride (floats)
#define BUFEL (BM * SKA)                // 4608 floats per operand buffer
#define SMEM_BYTES (2 * 4 * BUFEL * 4)  // 2 stages x 4 operands = 147456 B

// -------- device scratch (no cudaMalloc allowed) --------
__device__ float g_xhi[(size_t)MTOT * DIM];
__device__ float g_xlo[(size_t)MTOT * DIM];
__device__ float g_Whi[(size_t)3 * DIM * DIM];
__device__ float g_Wlo[(size_t)3 * DIM * DIM];
__device__ float g_Qhi[(size_t)MTOT * DIM];
__device__ float g_Qlo[(size_t)MTOT * DIM];
__device__ float g_Khi[(size_t)MTOT * DIM];
__device__ float g_Klo[(size_t)MTOT * DIM];
__device__ float g_Vthi[(size_t)MTOT * DIM];   // [b][dim][seq]
__device__ float g_Vtlo[(size_t)MTOT * DIM];
__device__ float g_Phi[(size_t)BATCH * SEQ * SEQ];
__device__ float g_Plo[(size_t)BATCH * SEQ * SEQ];
__device__ float g_cos[(size_t)SEQ * HALF_D];
__device__ float g_sin[(size_t)SEQ * HALF_D];

// ============================================================
// helpers
// ============================================================
__device__ __forceinline__ void split_tf32(float x, float& hi, float& lo) {
    uint32_t u;
    asm("cvt.rna.tf32.f32 %0, %1;" : "=r"(u) : "f"(x));
    hi = __uint_as_float(u);
    float r = x - hi;
    uint32_t v;
    asm("cvt.rna.tf32.f32 %0, %1;" : "=r"(v) : "f"(r));
    lo = __uint_as_float(v);
}

#define MMA_TF32(D, A, B)                                                   \
    asm volatile(                                                           \
        "mma.sync.aligned.m16n8k8.row.col.f32.tf32.tf32.f32 "               \
        "{%0,%1,%2,%3}, {%4,%5,%6,%7}, {%8,%9}, {%0,%1,%2,%3};"             \
        : "+f"((D)[0]), "+f"((D)[1]), "+f"((D)[2]), "+f"((D)[3])            \
        : "r"((A)[0]), "r"((A)[1]), "r"((A)[2]), "r"((A)[3]),               \
          "r"((B)[0]), "r"((B)[1]))

#define CP_ASYNC16(dst, src)                                                \
    asm volatile("cp.async.cg.shared.global [%0], [%1], 16;"                \
                 :: "r"(dst), "l"(src))
#define CP_COMMIT() asm volatile("cp.async.commit_group;")
#define CP_WAIT0()  asm volatile("cp.async.wait_group 0;")

// ============================================================
// RoPE cos/sin table (double precision generation)
// ============================================================
__global__ void trig_table_kernel(float* ct, float* st) {
    int idx = blockIdx.x * blockDim.x + threadIdx.x;
    if (idx >= SEQ * HALF_D) return;
    int s = idx / HALF_D;
    int j = idx % HALF_D;
    double inv = exp(-((double)(2 * j) / (double)DIM) * 9.210340371976184);
    double ang = (double)s * inv;
    double sv, cv;
    sincos(ang, &sv, &cv);
    ct[idx] = (float)cv;
    st[idx] = (float)sv;
}

// ============================================================
// Split fp32 array into tf32 hi/lo
// ============================================================
__global__ void split_kernel(const float* __restrict__ src,
                             float* __restrict__ hi, float* __restrict__ lo,
                             int n) {
    int i = blockIdx.x * blockDim.x + threadIdx.x;
    if (i >= n) return;
    float h, l;
    split_tf32(src[i], h, l);
    hi[i] = h;
    lo[i] = l;
}

// ============================================================
// 3xTF32 GEMM core: acc[m,n] += sum_k A[m,k]*B[n,k] (A,B pre-split)
// Tile BM x BN x K, double-buffered cp.async pipeline.
// ============================================================
__device__ __forceinline__ void gemm3_core(
    const float* __restrict__ Ahi, const float* __restrict__ Alo, int lda,
    const float* __restrict__ Bhi, const float* __restrict__ Blo, int ldb,
    int m0, int n0, int kSteps, float acc[4][4][4]) {
    extern __shared__ float smem[];
    const int tid = threadIdx.x;
    const int wid = tid >> 5;
    const int lane = tid & 31;
    const int grp = lane >> 2;
    const int tig = lane & 3;
    const int wm = (wid & 1) * 64;
    const int wn = (wid >> 1) * 32;

    uint32_t smem_u32 = (uint32_t)__cvta_generic_to_shared(smem);

#pragma unroll
    for (int mt = 0; mt < 4; mt++)
#pragma unroll
        for (int nt = 0; nt < 4; nt++)
#pragma unroll
            for (int c = 0; c < 4; c++) acc[mt][nt][c] = 0.0f;

    auto load_chunk = [&](int stage, int k0) {
#pragma unroll
        for (int i = 0; i < 4; i++) {
            int p = tid + NTHREADS * i;     // 0..1023
            int r = p >> 3;                 // 0..127
            int c = (p & 7) * 4;            // 0,4,...,28
            uint32_t base = smem_u32 + (uint32_t)(stage * 4 * BUFEL + r * SKA + c) * 4u;
            const float* ga_h = Ahi + (size_t)(m0 + r) * lda + k0 + c;
            const float* ga_l = Alo + (size_t)(m0 + r) * lda + k0 + c;
            const float* gb_h = Bhi + (size_t)(n0 + r) * ldb + k0 + c;
            const float* gb_l = Blo + (size_t)(n0 + r) * ldb + k0 + c;
            CP_ASYNC16(base + 0u * BUFEL * 4u, ga_h);
            CP_ASYNC16(base + 1u * BUFEL * 4u, ga_l);
            CP_ASYNC16(base + 2u * BUFEL * 4u, gb_h);
            CP_ASYNC16(base + 3u * BUFEL * 4u, gb_l);
        }
        CP_COMMIT();
    };

    // prologue
    load_chunk(0, 0);
    CP_WAIT0();
    __syncthreads();

    for (int it = 0; it < kSteps; it++) {
        int s = it & 1;
        if (it + 1 < kSteps) load_chunk((it + 1) & 1, (it + 1) * BK);

        const uint32_t* As_h = (const uint32_t*)smem + (s * 4 + 0) * BUFEL;
        const uint32_t* As_l = (const uint32_t*)smem + (s * 4 + 1) * BUFEL;
        const uint32_t* Bs_h = (const uint32_t*)smem + (s * 4 + 2) * BUFEL;
        const uint32_t* Bs_l = (const uint32_t*)smem + (s * 4 + 3) * BUFEL;

#pragma unroll
        for (int kt = 0; kt < 4; kt++) {
            const int kc = kt * 8 + tig;
            uint32_t ah[4][4], al[4][4];
#pragma unroll
            for (int mt = 0; mt < 4; mt++) {
                int r0 = (wm + mt * 16 + grp) * SKA;
                int r1 = r0 + 8 * SKA;
                ah[mt][0] = As_h[r0 + kc];
                ah[mt][1] = As_h[r1 + kc];
                ah[mt][2] = As_h[r0 + kc + 4];
                ah[mt][3] = As_h[r1 + kc + 4];
                al[mt][0] = As_l[r0 + kc];
                al[mt][1] = As_l[r1 + kc];
                al[mt][2] = As_l[r0 + kc + 4];
                al[mt][3] = As_l[r1 + kc + 4];
            }
            uint32_t bh[4][2], bl[4][2];
#pragma unroll
            for (int nt = 0; nt < 4; nt++) {
                int rn = (wn + nt * 8 + grp) * SKA;
                bh[nt][0] = Bs_h[rn + kc];
                bh[nt][1] = Bs_h[rn + kc + 4];
                bl[nt][0] = Bs_l[rn + kc];
                bl[nt][1] = Bs_l[rn + kc + 4];
            }
#pragma unroll
            for (int mt = 0; mt < 4; mt++)
#pragma unroll
                for (int nt = 0; nt < 4; nt++) {
                    MMA_TF32(acc[mt][nt], ah[mt], bh[nt]);
                    MMA_TF32(acc[mt][nt], ah[mt], bl[nt]);
                    MMA_TF32(acc[mt][nt], al[mt], bh[nt]);
                }
        }
        if (it + 1 < kSteps) CP_WAIT0();
        __syncthreads();
    }
}

// ============================================================
// QKV projection (3xTF32). mode 0: rope+split (Q/K). mode 1: transpose+split (V)
// grid = (DIM/BN, MTOT/BM)
// ============================================================
__global__ __launch_bounds__(NTHREADS, 1)
void qkv_mma_kernel(const float* __restrict__ Ahi, const float* __restrict__ Alo,
                    const float* __restrict__ Whi, const float* __restrict__ Wlo,
                    int mode,
                    float* __restrict__ Ohi, float* __restrict__ Olo,
                    const float* __restrict__ Ct, const float* __restrict__ St) {
    const int n0 = blockIdx.x * BN;
    const int m0 = blockIdx.y * BM;
    float acc[4][4][4];
    gemm3_core(Ahi, Alo, DIM, Whi, Wlo, DIM, m0, n0, DIM / BK, acc);

    const int tid = threadIdx.x;
    const int wid = tid >> 5;
    const int lane = tid & 31;
    const int grp = lane >> 2;
    const int tig = lane & 3;
    const int wm = (wid & 1) * 64;
    const int wn = (wid >> 1) * 32;

#pragma unroll
    for (int mt = 0; mt < 4; mt++)
#pragma unroll
        for (int nt = 0; nt < 4; nt++)
#pragma unroll
            for (int h = 0; h < 2; h++) {
                int row = m0 + wm + mt * 16 + grp + 8 * h;
                int colE = n0 + wn + nt * 8 + tig * 2;
                float e = acc[mt][nt][2 * h];
                float o = acc[mt][nt][2 * h + 1];
                if (mode == 0) {
                    int s = row & (SEQ - 1);
                    int j = colE >> 1;
                    float cth = Ct[(size_t)s * HALF_D + j];
                    float sth = St[(size_t)s * HALF_D + j];
                    float re = e * cth - o * sth;
                    float ro = e * sth + o * cth;
                    float h1, l1, h2, l2;
                    split_tf32(re, h1, l1);
                    split_tf32(ro, h2, l2);
                    size_t p = (size_t)row * DIM + colE;
                    Ohi[p] = h1; Olo[p] = l1;
                    Ohi[p + 1] = h2; Olo[p + 1] = l2;
                } else {
                    // transpose: Vt[b][col][s]
                    int b = row >> 12;
                    int s = row & (SEQ - 1);
                    float h1, l1, h2, l2;
                    split_tf32(e, h1, l1);
                    split_tf32(o, h2, l2);
                    size_t p0 = ((size_t)b * DIM + colE) * SEQ + s;
                    size_t p1 = ((size_t)b * DIM + colE + 1) * SEQ + s;
                    Ohi[p0] = h1; Olo[p0] = l1;
                    Ohi[p1] = h2; Olo[p1] = l2;
                }
            }
}

// ============================================================
// Scores (3xTF32): P = (Q K^T)/32, lower-triangle tiles, split output.
// grid = (SEQ/BN, SEQ/BM, BATCH)
// ============================================================
__global__ __launch_bounds__(NTHREADS, 1)
void scores_mma_kernel(const float* __restrict__ Qhi, const float* __restrict__ Qlo,
                       const float* __restrict__ Khi, const float* __restrict__ Klo,
                       float* __restrict__ Phi, float* __restrict__ Plo) {
    const int n0 = blockIdx.x * BN;
    const int m0 = blockIdx.y * BM;
    if (n0 > m0) return;
    const int b = blockIdx.z;
    const size_t boff = (size_t)b * SEQ * DIM;

    float acc[4][4][4];
    gemm3_core(Qhi + boff, Qlo + boff, DIM, Khi + boff, Klo + boff, DIM,
               m0, n0, DIM / BK, acc);

    const int tid = threadIdx.x;
    const int wid = tid >> 5;
    const int lane = tid & 31;
    const int grp = lane >> 2;
    const int tig = lane & 3;
    const int wm = (wid & 1) * 64;
    const int wn = (wid >> 1) * 32;
    const float scale = 1.0f / 32.0f;

    float* Pbh = Phi + (size_t)b * SEQ * SEQ;
    float* Pbl = Plo + (size_t)b * SEQ * SEQ;
#pragma unroll
    for (int mt = 0; mt < 4; mt++)
#pragma unroll
        for (int nt = 0; nt < 4; nt++)
#pragma unroll
            for (int c = 0; c < 4; c++) {
                int row = m0 + wm + mt * 16 + grp + ((c >> 1) << 3);
                int col = n0 + wn + nt * 8 + tig * 2 + (c & 1);
                float h, l;
                split_tf32(acc[mt][nt][c] * scale, h, l);
                size_t p = (size_t)row * SEQ + col;
                Pbh[p] = h;
                Pbl[p] = l;
            }
}

// ============================================================
// Causal softmax over split P, writes split probs + zero-pad to tile edge
// ============================================================
__global__ __launch_bounds__(NTHREADS)
void softmax_kernel(float* __restrict__ Phi, float* __restrict__ Plo) {
    __shared__ float red[NTHREADS];
    const int rowg = blockIdx.x;
    const int b = rowg >> 12;
    const int i = rowg & (SEQ - 1);
    float* ph = Phi + ((size_t)b * SEQ + i) * SEQ;
    float* pl = Plo + ((size_t)b * SEQ + i) * SEQ;
    const int L = i + 1;
    const int tid = threadIdx.x;

    float m = -3.0e38f;
    for (int j = tid; j < L; j += NTHREADS) m = fmaxf(m, ph[j] + pl[j]);
    red[tid] = m; __syncthreads();
    for (int s2 = NTHREADS / 2; s2 > 0; s2 >>= 1) {
        if (tid < s2) red[tid] = fmaxf(red[tid], red[tid + s2]);
        __syncthreads();
    }
    m = red[0]; __syncthreads();

    float sum = 0.0f;
    for (int j = tid; j < L; j += NTHREADS) {
        float e = expf(ph[j] + pl[j] - m);
        ph[j] = e;       // stash un-normalized, full fp32 precision
        sum += e;
    }
    red[tid] = sum; __syncthreads();
    for (int s2 = NTHREADS / 2; s2 > 0; s2 >>= 1) {
        if (tid < s2) red[tid] += red[tid + s2];
        __syncthreads();
    }
    const float inv = 1.0f / red[0];
    for (int j = tid; j < L; j += NTHREADS) {
        float h, l;
        split_tf32(ph[j] * inv, h, l);
        ph[j] = h;
        pl[j] = l;
    }
    const int bound = (i & ~127) + 128;
    for (int j = L + tid; j < bound; j += NTHREADS) { ph[j] = 0.0f; pl[j] = 0.0f; }
}

// ============================================================
// PV (3xTF32): O = P @ V using Vt (K-major), causal-truncated k-loop.
// grid = (DIM/BN, SEQ/BM, BATCH)
// ============================================================
__global__ __launch_bounds__(NTHREADS, 1)
void pv_mma_kernel(const float* __restrict__ Phi, const float* __restrict__ Plo,
                   const float* __restrict__ Vthi, const float* __restrict__ Vtlo,
                   float* __restrict__ O) {
    const int n0 = blockIdx.x * BN;
    const int m0 = blockIdx.y * BM;
    const int b = blockIdx.z;

    const float* Ah = Phi + (size_t)b * SEQ * SEQ;
    const float* Al = Plo + (size_t)b * SEQ * SEQ;
    const float* Bh = Vthi + (size_t)b * DIM * SEQ;
    const float* Bl = Vtlo + (size_t)b * DIM * SEQ;

    float acc[4][4][4];
    gemm3_core(Ah, Al, SEQ, Bh, Bl, SEQ, m0, n0, (m0 + BM) / BK, acc);

    const int tid = threadIdx.x;
    const int wid = tid >> 5;
    const int lane = tid & 31;
    const int grp = lane >> 2;
    const int tig = lane & 3;
    const int wm = (wid & 1) * 64;
    const int wn = (wid >> 1) * 32;

#pragma unroll
    for (int mt = 0; mt < 4; mt++)
#pragma unroll
        for (int nt = 0; nt < 4; nt++)
#pragma unroll
            for (int c = 0; c < 4; c++) {
                int row = m0 + wm + mt * 16 + grp + ((c >> 1) << 3);
                int col = n0 + wn + nt * 8 + tig * 2 + (c & 1);
                O[((size_t)b * SEQ + row) * DIM + col] = acc[mt][nt][c];
            }
}

// ============================================================
// Launch
// ============================================================
extern "C" void kernel_launch(void* const* d_in, const int* in_sizes, int n_in,
                              void* d_out, int out_size) {
    const float* x  = (const float*)d_in[0];
    const float* Wq = (const float*)d_in[1];
    const float* Wk = (const float*)d_in[2];
    const float* Wv = (const float*)d_in[3];
    float* out = (float*)d_out;

    float *xh, *xl, *Wh, *Wl, *Qh, *Ql, *Kh, *Kl, *Vth, *Vtl, *Ph, *Pl, *Cp, *Sp;
    cudaGetSymbolAddress((void**)&xh, g_xhi);
    cudaGetSymbolAddress((void**)&xl, g_xlo);
    cudaGetSymbolAddress((void**)&Wh, g_Whi);
    cudaGetSymbolAddress((void**)&Wl, g_Wlo);
    cudaGetSymbolAddress((void**)&Qh, g_Qhi);
    cudaGetSymbolAddress((void**)&Ql, g_Qlo);
    cudaGetSymbolAddress((void**)&Kh, g_Khi);
    cudaGetSymbolAddress((void**)&Kl, g_Klo);
    cudaGetSymbolAddress((void**)&Vth, g_Vthi);
    cudaGetSymbolAddress((void**)&Vtl, g_Vtlo);
    cudaGetSymbolAddress((void**)&Ph, g_Phi);
    cudaGetSymbolAddress((void**)&Pl, g_Plo);
    cudaGetSymbolAddress((void**)&Cp, g_cos);
    cudaGetSymbolAddress((void**)&Sp, g_sin);

    // Opt-in dynamic SMEM (idempotent)
    cudaFuncSetAttribute(qkv_mma_kernel,    cudaFuncAttributeMaxDynamicSharedMemorySize, SMEM_BYTES);
    cudaFuncSetAttribute(scores_mma_kernel, cudaFuncAttributeMaxDynamicSharedMemorySize, SMEM_BYTES);
    cudaFuncSetAttribute(pv_mma_kernel,     cudaFuncAttributeMaxDynamicSharedMemorySize, SMEM_BYTES);

    // 1) trig tables
    {
        int total = SEQ * HALF_D;
        trig_table_kernel<<<(total + 255) / 256, 256>>>(Cp, Sp);
    }

    // 2) split inputs to tf32 hi/lo
    {
        int nx = MTOT * DIM;
        split_kernel<<<(nx + 255) / 256, 256>>>(x, xh, xl, nx);
        int nw = DIM * DIM;
        split_kernel<<<(nw + 255) / 256, 256>>>(Wq, Wh + 0 * (size_t)nw, Wl + 0 * (size_t)nw, nw);
        split_kernel<<<(nw + 255) / 256, 256>>>(Wk, Wh + 1 * (size_t)nw, Wl + 1 * (size_t)nw, nw);
        split_kernel<<<(nw + 255) / 256, 256>>>(Wv, Wh + 2 * (size_t)nw, Wl + 2 * (size_t)nw, nw);
    }

    // 3) projections (rope fused for Q,K; transpose fused for V)
    {
        dim3 grid(DIM / BN, MTOT / BM);   // (8, 128)
        size_t nw = (size_t)DIM * DIM;
        qkv_mma_kernel<<<grid, NTHREADS, SMEM_BYTES>>>(xh, xl, Wh + 0 * nw, Wl + 0 * nw, 0, Qh, Ql, Cp, Sp);
        qkv_mma_kernel<<<grid, NTHREADS, SMEM_BYTES>>>(xh, xl, Wh + 1 * nw, Wl + 1 * nw, 0, Kh, Kl, Cp, Sp);
        qkv_mma_kernel<<<grid, NTHREADS, SMEM_BYTES>>>(xh, xl, Wh + 2 * nw, Wl + 2 * nw, 1, Vth, Vtl, Cp, Sp);
    }

    // 4) causal scores (split output)
    {
        dim3 grid(SEQ / BN, SEQ / BM, BATCH);
        scores_mma_kernel<<<grid, NTHREADS, SMEM_BYTES>>>(Qh, Ql, Kh, Kl, Ph, Pl);
    }

    // 5) softmax (split in place + pad)
    softmax_kernel<<<BATCH * SEQ, NTHREADS>>>(Ph, Pl);

    // 6) O = P @ V
    {
        dim3 grid(DIM / BN, SEQ / BM, BATCH);
        pv_mma_kernel<<<grid, NTHREADS, SMEM_BYTES>>>(Ph, Pl, Vth, Vtl, out);
    }
}

// round 6
// speedup vs baseline: 2.2808x; 1.6286x over previous
#include <cuda_runtime.h>
#include <cuda_bf16.h>
#include <math.h>
#include <stdint.h>

typedef __nv_bfloat16 bf16;
typedef __nv_bfloat162 bf162;

// Problem constants
#define BATCH 4
#define SEQ   4096
#define DIM   1024
#define MTOT  (BATCH * SEQ)     // 16384
#define HALF_D (DIM / 2)        // 512

// GEMM tiling
#define BM 128
#define BN 128
#define BK 32
#define NTHREADS 256
#define SKB 40                          // padded smem row stride (bf16 elems) = 20 words
#define BUFB (BM * SKB)                 // 5120 bf16 per operand buffer
#define SMEM_BYTES (2 * 4 * BUFB * 2)   // 2 stages x 4 operands x bf16 = 81920 B

// -------- device scratch (no cudaMalloc allowed) --------
__device__ bf16 g_xhi[(size_t)MTOT * DIM];
__device__ bf16 g_xlo[(size_t)MTOT * DIM];
__device__ bf16 g_Whi[(size_t)3 * DIM * DIM];
__device__ bf16 g_Wlo[(size_t)3 * DIM * DIM];
__device__ bf16 g_Qhi[(size_t)MTOT * DIM];
__device__ bf16 g_Qlo[(size_t)MTOT * DIM];
__device__ bf16 g_Khi[(size_t)MTOT * DIM];
__device__ bf16 g_Klo[(size_t)MTOT * DIM];
__device__ bf16 g_Vthi[(size_t)MTOT * DIM];   // [b][dim][seq]
__device__ bf16 g_Vtlo[(size_t)MTOT * DIM];
__device__ float g_Ps[(size_t)BATCH * SEQ * SEQ];   // fp32 scores / unnormalized probs
__device__ bf16 g_Pbh[(size_t)BATCH * SEQ * SEQ];   // split probs for PV
__device__ bf16 g_Pbl[(size_t)BATCH * SEQ * SEQ];
__device__ float g_cos[(size_t)SEQ * HALF_D];
__device__ float g_sin[(size_t)SEQ * HALF_D];

// ============================================================
// helpers
// ============================================================
__device__ __forceinline__ void split_bf16(float x, bf16& hi, bf16& lo) {
    hi = __float2bfloat16_rn(x);
    lo = __float2bfloat16_rn(x - __bfloat162float(hi));
}

#define MMA_BF16(D, A, B)                                                   \
    asm volatile(                                                           \
        "mma.sync.aligned.m16n8k16.row.col.f32.bf16.bf16.f32 "              \
        "{%0,%1,%2,%3}, {%4,%5,%6,%7}, {%8,%9}, {%0,%1,%2,%3};"             \
        : "+f"((D)[0]), "+f"((D)[1]), "+f"((D)[2]), "+f"((D)[3])            \
        : "r"((A)[0]), "r"((A)[1]), "r"((A)[2]), "r"((A)[3]),               \
          "r"((B)[0]), "r"((B)[1]))

#define CP_ASYNC16(dst, src)                                                \
    asm volatile("cp.async.cg.shared.global [%0], [%1], 16;"                \
                 :: "r"(dst), "l"(src))
#define CP_COMMIT() asm volatile("cp.async.commit_group;")
#define CP_WAIT0()  asm volatile("cp.async.wait_group 0;")

// ============================================================
// RoPE cos/sin table (double precision generation)
// ============================================================
__global__ void trig_table_kernel(float* ct, float* st) {
    int idx = blockIdx.x * blockDim.x + threadIdx.x;
    if (idx >= SEQ * HALF_D) return;
    int s = idx / HALF_D;
    int j = idx % HALF_D;
    double inv = exp(-((double)(2 * j) / (double)DIM) * 9.210340371976184);
    double ang = (double)s * inv;
    double sv, cv;
    sincos(ang, &sv, &cv);
    ct[idx] = (float)cv;
    st[idx] = (float)sv;
}

// ============================================================
// Split fp32 array into bf16 hi/lo
// ============================================================
__global__ void split_kernel(const float* __restrict__ src,
                             bf16* __restrict__ hi, bf16* __restrict__ lo,
                             int n) {
    int i = blockIdx.x * blockDim.x + threadIdx.x;
    if (i >= n) return;
    bf16 h, l;
    split_bf16(src[i], h, l);
    hi[i] = h;
    lo[i] = l;
}

// ============================================================
// 3xBF16 GEMM core: acc[m,n] += sum_k A[m,k]*B[n,k] (A,B pre-split)
// Tile BM x BN x K, double-buffered cp.async pipeline.
// ============================================================
__device__ __forceinline__ void gemm3_core(
    const bf16* __restrict__ Ahi, const bf16* __restrict__ Alo, int lda,
    const bf16* __restrict__ Bhi, const bf16* __restrict__ Blo, int ldb,
    int m0, int n0, int kSteps, float acc[4][4][4]) {
    extern __shared__ bf16 smem[];
    const int tid = threadIdx.x;
    const int wid = tid >> 5;
    const int lane = tid & 31;
    const int grp = lane >> 2;
    const int tig = lane & 3;
    const int wm = (wid & 1) * 64;
    const int wn = (wid >> 1) * 32;

    uint32_t smem_u32 = (uint32_t)__cvta_generic_to_shared(smem);

#pragma unroll
    for (int mt = 0; mt < 4; mt++)
#pragma unroll
        for (int nt = 0; nt < 4; nt++)
#pragma unroll
            for (int c = 0; c < 4; c++) acc[mt][nt][c] = 0.0f;

    const bf16* srcs[4];
    srcs[0] = Ahi + (size_t)m0 * lda;
    srcs[1] = Alo + (size_t)m0 * lda;
    srcs[2] = Bhi + (size_t)n0 * ldb;
    srcs[3] = Blo + (size_t)n0 * ldb;
    int ldsz[4] = {lda, lda, ldb, ldb};

    auto load_chunk = [&](int stage, int k0) {
#pragma unroll
        for (int i = 0; i < 8; i++) {
            const int op = i >> 1;
            const int q = tid + NTHREADS * (i & 1);  // 0..511 per operand
            const int r = q >> 2;                    // row 0..127
            const int c = (q & 3) * 8;               // bf16 col 0,8,16,24
            uint32_t dst = smem_u32 +
                (uint32_t)(((stage * 4 + op) * BUFB + r * SKB + c) * 2);
            const bf16* src = srcs[op] + (size_t)r * ldsz[op] + k0 + c;
            CP_ASYNC16(dst, src);
        }
        CP_COMMIT();
    };

    // prologue
    load_chunk(0, 0);
    CP_WAIT0();
    __syncthreads();

    for (int it = 0; it < kSteps; it++) {
        int s = it & 1;
        if (it + 1 < kSteps) load_chunk((it + 1) & 1, (it + 1) * BK);

        const uint32_t* As_h = (const uint32_t*)smem + (s * 4 + 0) * (BUFB / 2);
        const uint32_t* As_l = (const uint32_t*)smem + (s * 4 + 1) * (BUFB / 2);
        const uint32_t* Bs_h = (const uint32_t*)smem + (s * 4 + 2) * (BUFB / 2);
        const uint32_t* Bs_l = (const uint32_t*)smem + (s * 4 + 3) * (BUFB / 2);
        const int RW = SKB / 2;   // 20 words per row

#pragma unroll
        for (int kc = 0; kc < 2; kc++) {          // two k16 chunks per BK=32
            const int wb = kc * 8 + tig;
            uint32_t ah[4][4], al[4][4];
#pragma unroll
            for (int mt = 0; mt < 4; mt++) {
                int r0 = (wm + mt * 16 + grp) * RW;
                int r1 = r0 + 8 * RW;
                ah[mt][0] = As_h[r0 + wb];
                ah[mt][1] = As_h[r1 + wb];
                ah[mt][2] = As_h[r0 + wb + 4];
                ah[mt][3] = As_h[r1 + wb + 4];
                al[mt][0] = As_l[r0 + wb];
                al[mt][1] = As_l[r1 + wb];
                al[mt][2] = As_l[r0 + wb + 4];
                al[mt][3] = As_l[r1 + wb + 4];
            }
            uint32_t bh[4][2], bl[4][2];
#pragma unroll
            for (int nt = 0; nt < 4; nt++) {
                int rn = (wn + nt * 8 + grp) * RW;
                bh[nt][0] = Bs_h[rn + wb];
                bh[nt][1] = Bs_h[rn + wb + 4];
                bl[nt][0] = Bs_l[rn + wb];
                bl[nt][1] = Bs_l[rn + wb + 4];
            }
#pragma unroll
            for (int mt = 0; mt < 4; mt++)
#pragma unroll
                for (int nt = 0; nt < 4; nt++) {
                    MMA_BF16(acc[mt][nt], ah[mt], bh[nt]);
                    MMA_BF16(acc[mt][nt], ah[mt], bl[nt]);
                    MMA_BF16(acc[mt][nt], al[mt], bh[nt]);
                }
        }
        if (it + 1 < kSteps) CP_WAIT0();
        __syncthreads();
    }
}

// ============================================================
// QKV projection. mode 0: rope+split (Q/K). mode 1: transpose+split (V)
// grid = (DIM/BN, MTOT/BM)
// ============================================================
__global__ __launch_bounds__(NTHREADS, 1)
void qkv_mma_kernel(const bf16* __restrict__ Ahi, const bf16* __restrict__ Alo,
                    const bf16* __restrict__ Whi, const bf16* __restrict__ Wlo,
                    int mode,
                    bf16* __restrict__ Ohi, bf16* __restrict__ Olo,
                    const float* __restrict__ Ct, const float* __restrict__ St) {
    const int n0 = blockIdx.x * BN;
    const int m0 = blockIdx.y * BM;
    float acc[4][4][4];
    gemm3_core(Ahi, Alo, DIM, Whi, Wlo, DIM, m0, n0, DIM / BK, acc);

    const int tid = threadIdx.x;
    const int wid = tid >> 5;
    const int lane = tid & 31;
    const int grp = lane >> 2;
    const int tig = lane & 3;
    const int wm = (wid & 1) * 64;
    const int wn = (wid >> 1) * 32;

#pragma unroll
    for (int mt = 0; mt < 4; mt++)
#pragma unroll
        for (int nt = 0; nt < 4; nt++)
#pragma unroll
            for (int h = 0; h < 2; h++) {
                int row = m0 + wm + mt * 16 + grp + 8 * h;
                int colE = n0 + wn + nt * 8 + tig * 2;
                float e = acc[mt][nt][2 * h];
                float o = acc[mt][nt][2 * h + 1];
                if (mode == 0) {
                    int s = row & (SEQ - 1);
                    int j = colE >> 1;
                    float cth = Ct[(size_t)s * HALF_D + j];
                    float sth = St[(size_t)s * HALF_D + j];
                    float re = e * cth - o * sth;
                    float ro = e * sth + o * cth;
                    bf16 h1, l1, h2, l2;
                    split_bf16(re, h1, l1);
                    split_bf16(ro, h2, l2);
                    size_t p = (size_t)row * DIM + colE;
                    *(bf162*)(Ohi + p) = bf162{h1, h2};
                    *(bf162*)(Olo + p) = bf162{l1, l2};
                } else {
                    // transpose: Vt[b][col][s]
                    int b = row >> 12;
                    int s = row & (SEQ - 1);
                    bf16 h1, l1, h2, l2;
                    split_bf16(e, h1, l1);
                    split_bf16(o, h2, l2);
                    size_t p0 = ((size_t)b * DIM + colE) * SEQ + s;
                    size_t p1 = ((size_t)b * DIM + colE + 1) * SEQ + s;
                    Ohi[p0] = h1; Olo[p0] = l1;
                    Ohi[p1] = h2; Olo[p1] = l2;
                }
            }
}

// ============================================================
// Scores: P = (Q K^T)/32, lower-triangle tiles, fp32 output.
// grid = (SEQ/BN, SEQ/BM, BATCH)
// ============================================================
__global__ __launch_bounds__(NTHREADS, 1)
void scores_mma_kernel(const bf16* __restrict__ Qhi, const bf16* __restrict__ Qlo,
                       const bf16* __restrict__ Khi, const bf16* __restrict__ Klo,
                       float* __restrict__ Ps) {
    const int n0 = blockIdx.x * BN;
    const int m0 = blockIdx.y * BM;
    if (n0 > m0) return;
    const int b = blockIdx.z;
    const size_t boff = (size_t)b * SEQ * DIM;

    float acc[4][4][4];
    gemm3_core(Qhi + boff, Qlo + boff, DIM, Khi + boff, Klo + boff, DIM,
               m0, n0, DIM / BK, acc);

    const int tid = threadIdx.x;
    const int wid = tid >> 5;
    const int lane = tid & 31;
    const int grp = lane >> 2;
    const int tig = lane & 3;
    const int wm = (wid & 1) * 64;
    const int wn = (wid >> 1) * 32;
    const float scale = 1.0f / 32.0f;

    float* Pb = Ps + (size_t)b * SEQ * SEQ;
#pragma unroll
    for (int mt = 0; mt < 4; mt++)
#pragma unroll
        for (int nt = 0; nt < 4; nt++)
#pragma unroll
            for (int h = 0; h < 2; h++) {
                int row = m0 + wm + mt * 16 + grp + 8 * h;
                int col = n0 + wn + nt * 8 + tig * 2;
                float2 v;
                v.x = acc[mt][nt][2 * h] * scale;
                v.y = acc[mt][nt][2 * h + 1] * scale;
                *(float2*)(Pb + (size_t)row * SEQ + col) = v;
            }
}

// ============================================================
// Causal softmax: fp32 scores in, bf16 hi/lo probs out (+zero pad)
// ============================================================
__global__ __launch_bounds__(NTHREADS)
void softmax_kernel(float* __restrict__ Ps,
                    bf16* __restrict__ Pbh, bf16* __restrict__ Pbl) {
    __shared__ float red[NTHREADS];
    const int rowg = blockIdx.x;
    const int b = rowg >> 12;
    const int i = rowg & (SEQ - 1);
    float* p = Ps + ((size_t)b * SEQ + i) * SEQ;
    bf16* ph = Pbh + ((size_t)b * SEQ + i) * SEQ;
    bf16* pl = Pbl + ((size_t)b * SEQ + i) * SEQ;
    const int L = i + 1;
    const int tid = threadIdx.x;

    float m = -3.0e38f;
    for (int j = tid; j < L; j += NTHREADS) m = fmaxf(m, p[j]);
    red[tid] = m; __syncthreads();
    for (int s2 = NTHREADS / 2; s2 > 0; s2 >>= 1) {
        if (tid < s2) red[tid] = fmaxf(red[tid], red[tid + s2]);
        __syncthreads();
    }
    m = red[0]; __syncthreads();

    float sum = 0.0f;
    for (int j = tid; j < L; j += NTHREADS) {
        float e = expf(p[j] - m);
        p[j] = e;       // full fp32 precision stash
        sum += e;
    }
    red[tid] = sum; __syncthreads();
    for (int s2 = NTHREADS / 2; s2 > 0; s2 >>= 1) {
        if (tid < s2) red[tid] += red[tid + s2];
        __syncthreads();
    }
    const float inv = 1.0f / red[0];
    for (int j = tid; j < L; j += NTHREADS) {
        bf16 h, l;
        split_bf16(p[j] * inv, h, l);
        ph[j] = h;
        pl[j] = l;
    }
    const int bound = (i & ~127) + 128;
    for (int j = L + tid; j < bound; j += NTHREADS) {
        ph[j] = __float2bfloat16(0.0f);
        pl[j] = __float2bfloat16(0.0f);
    }
}

// ============================================================
// PV: O = P @ V using Vt (K-major), causal-truncated k-loop.
// grid = (DIM/BN, SEQ/BM, BATCH)
// ============================================================
__global__ __launch_bounds__(NTHREADS, 1)
void pv_mma_kernel(const bf16* __restrict__ Pbh, const bf16* __restrict__ Pbl,
                   const bf16* __restrict__ Vthi, const bf16* __restrict__ Vtlo,
                   float* __restrict__ O) {
    const int n0 = blockIdx.x * BN;
    const int m0 = blockIdx.y * BM;
    const int b = blockIdx.z;

    const bf16* Ah = Pbh + (size_t)b * SEQ * SEQ;
    const bf16* Al = Pbl + (size_t)b * SEQ * SEQ;
    const bf16* Bh = Vthi + (size_t)b * DIM * SEQ;
    const bf16* Bl = Vtlo + (size_t)b * DIM * SEQ;

    float acc[4][4][4];
    gemm3_core(Ah, Al, SEQ, Bh, Bl, SEQ, m0, n0, (m0 + BM) / BK, acc);

    const int tid = threadIdx.x;
    const int wid = tid >> 5;
    const int lane = tid & 31;
    const int grp = lane >> 2;
    const int tig = lane & 3;
    const int wm = (wid & 1) * 64;
    const int wn = (wid >> 1) * 32;

#pragma unroll
    for (int mt = 0; mt < 4; mt++)
#pragma unroll
        for (int nt = 0; nt < 4; nt++)
#pragma unroll
            for (int h = 0; h < 2; h++) {
                int row = m0 + wm + mt * 16 + grp + 8 * h;
                int col = n0 + wn + nt * 8 + tig * 2;
                float2 v;
                v.x = acc[mt][nt][2 * h];
                v.y = acc[mt][nt][2 * h + 1];
                *(float2*)(O + ((size_t)b * SEQ + row) * DIM + col) = v;
            }
}

// ============================================================
// Launch
// ============================================================
extern "C" void kernel_launch(void* const* d_in, const int* in_sizes, int n_in,
                              void* d_out, int out_size) {
    const float* x  = (const float*)d_in[0];
    const float* Wq = (const float*)d_in[1];
    const float* Wk = (const float*)d_in[2];
    const float* Wv = (const float*)d_in[3];
    float* out = (float*)d_out;

    bf16 *xh, *xl, *Wh, *Wl, *Qh, *Ql, *Kh, *Kl, *Vth, *Vtl, *Pbh, *Pbl;
    float *Psf, *Cp, *Sp;
    cudaGetSymbolAddress((void**)&xh, g_xhi);
    cudaGetSymbolAddress((void**)&xl, g_xlo);
    cudaGetSymbolAddress((void**)&Wh, g_Whi);
    cudaGetSymbolAddress((void**)&Wl, g_Wlo);
    cudaGetSymbolAddress((void**)&Qh, g_Qhi);
    cudaGetSymbolAddress((void**)&Ql, g_Qlo);
    cudaGetSymbolAddress((void**)&Kh, g_Khi);
    cudaGetSymbolAddress((void**)&Kl, g_Klo);
    cudaGetSymbolAddress((void**)&Vth, g_Vthi);
    cudaGetSymbolAddress((void**)&Vtl, g_Vtlo);
    cudaGetSymbolAddress((void**)&Psf, g_Ps);
    cudaGetSymbolAddress((void**)&Pbh, g_Pbh);
    cudaGetSymbolAddress((void**)&Pbl, g_Pbl);
    cudaGetSymbolAddress((void**)&Cp, g_cos);
    cudaGetSymbolAddress((void**)&Sp, g_sin);

    cudaFuncSetAttribute(qkv_mma_kernel,    cudaFuncAttributeMaxDynamicSharedMemorySize, SMEM_BYTES);
    cudaFuncSetAttribute(scores_mma_kernel, cudaFuncAttributeMaxDynamicSharedMemorySize, SMEM_BYTES);
    cudaFuncSetAttribute(pv_mma_kernel,     cudaFuncAttributeMaxDynamicSharedMemorySize, SMEM_BYTES);

    // 1) trig tables
    {
        int total = SEQ * HALF_D;
        trig_table_kernel<<<(total + 255) / 256, 256>>>(Cp, Sp);
    }

    // 2) split inputs to bf16 hi/lo
    {
        int nx = MTOT * DIM;
        split_kernel<<<(nx + 255) / 256, 256>>>(x, xh, xl, nx);
        int nw = DIM * DIM;
        split_kernel<<<(nw + 255) / 256, 256>>>(Wq, Wh + 0 * (size_t)nw, Wl + 0 * (size_t)nw, nw);
        split_kernel<<<(nw + 255) / 256, 256>>>(Wk, Wh + 1 * (size_t)nw, Wl + 1 * (size_t)nw, nw);
        split_kernel<<<(nw + 255) / 256, 256>>>(Wv, Wh + 2 * (size_t)nw, Wl + 2 * (size_t)nw, nw);
    }

    // 3) projections (rope fused for Q,K; transpose fused for V)
    {
        dim3 grid(DIM / BN, MTOT / BM);   // (8, 128)
        size_t nw = (size_t)DIM * DIM;
        qkv_mma_kernel<<<grid, NTHREADS, SMEM_BYTES>>>(xh, xl, Wh + 0 * nw, Wl + 0 * nw, 0, Qh, Ql, Cp, Sp);
        qkv_mma_kernel<<<grid, NTHREADS, SMEM_BYTES>>>(xh, xl, Wh + 1 * nw, Wl + 1 * nw, 0, Kh, Kl, Cp, Sp);
        qkv_mma_kernel<<<grid, NTHREADS, SMEM_BYTES>>>(xh, xl, Wh + 2 * nw, Wl + 2 * nw, 1, Vth, Vtl, Cp, Sp);
    }

    // 4) causal scores (fp32 output)
    {
        dim3 grid(SEQ / BN, SEQ / BM, BATCH);
        scores_mma_kernel<<<grid, NTHREADS, SMEM_BYTES>>>(Qh, Ql, Kh, Kl, Psf);
    }

    // 5) softmax (fp32 in, split bf16 out + pad)
    softmax_kernel<<<BATCH * SEQ, NTHREADS>>>(Psf, Pbh, Pbl);

    // 6) O = P @ V
    {
        dim3 grid(DIM / BN, SEQ / BM, BATCH);
        pv_mma_kernel<<<grid, NTHREADS, SMEM_BYTES>>>(Pbh, Pbl, Vth, Vtl, out);
    }
}

// round 7
// speedup vs baseline: 2.4539x; 1.0759x over previous
#include <cuda_runtime.h>
#include <cuda_bf16.h>
#include <math.h>
#include <stdint.h>

typedef __nv_bfloat16 bf16;
typedef __nv_bfloat162 bf162;

// Problem constants
#define BATCH 4
#define SEQ   4096
#define DIM   1024
#define MTOT  (BATCH * SEQ)     // 16384
#define HALF_D (DIM / 2)        // 512

// GEMM tiling
#define BM 128
#define BN 128
#define BK 32
#define NTHREADS 256
#define SKB 40                          // padded smem row stride (bf16 elems) = 20 words
#define BUFB (BM * SKB)                 // 5120 bf16 per operand buffer
#define SMEM_BYTES (2 * 4 * BUFB * 2)   // 2 stages x 4 operands x bf16 = 81920 B

// -------- device scratch (no cudaMalloc allowed) --------
__device__ bf16 g_xhi[(size_t)MTOT * DIM];
__device__ bf16 g_xlo[(size_t)MTOT * DIM];
__device__ bf16 g_Whi[(size_t)3 * DIM * DIM];
__device__ bf16 g_Wlo[(size_t)3 * DIM * DIM];
__device__ bf16 g_Qhi[(size_t)MTOT * DIM];
__device__ bf16 g_Qlo[(size_t)MTOT * DIM];
__device__ bf16 g_Khi[(size_t)MTOT * DIM];
__device__ bf16 g_Klo[(size_t)MTOT * DIM];
__device__ bf16 g_Vthi[(size_t)MTOT * DIM];   // [b][dim][seq]
__device__ bf16 g_Vtlo[(size_t)MTOT * DIM];
__device__ float g_Ps[(size_t)BATCH * SEQ * SEQ];   // fp32 scores
__device__ bf16 g_Pbh[(size_t)BATCH * SEQ * SEQ];   // split probs for PV
__device__ bf16 g_Pbl[(size_t)BATCH * SEQ * SEQ];
__device__ float g_cos[(size_t)SEQ * HALF_D];
__device__ float g_sin[(size_t)SEQ * HALF_D];

// ============================================================
// helpers
// ============================================================
__device__ __forceinline__ void split_bf16(float x, bf16& hi, bf16& lo) {
    hi = __float2bfloat16_rn(x);
    lo = __float2bfloat16_rn(x - __bfloat162float(hi));
}

#define MMA_BF16(D, A, B)                                                   \
    asm volatile(                                                           \
        "mma.sync.aligned.m16n8k16.row.col.f32.bf16.bf16.f32 "              \
        "{%0,%1,%2,%3}, {%4,%5,%6,%7}, {%8,%9}, {%0,%1,%2,%3};"             \
        : "+f"((D)[0]), "+f"((D)[1]), "+f"((D)[2]), "+f"((D)[3])            \
        : "r"((A)[0]), "r"((A)[1]), "r"((A)[2]), "r"((A)[3]),               \
          "r"((B)[0]), "r"((B)[1]))

#define CP_ASYNC16(dst, src)                                                \
    asm volatile("cp.async.cg.shared.global [%0], [%1], 16;"                \
                 :: "r"(dst), "l"(src))
#define CP_COMMIT() asm volatile("cp.async.commit_group;")
#define CP_WAIT0()  asm volatile("cp.async.wait_group 0;")

// ============================================================
// RoPE cos/sin table (double precision generation)
// ============================================================
__global__ void trig_table_kernel(float* ct, float* st) {
    int idx = blockIdx.x * blockDim.x + threadIdx.x;
    if (idx >= SEQ * HALF_D) return;
    int s = idx / HALF_D;
    int j = idx % HALF_D;
    double inv = exp(-((double)(2 * j) / (double)DIM) * 9.210340371976184);
    double ang = (double)s * inv;
    double sv, cv;
    sincos(ang, &sv, &cv);
    ct[idx] = (float)cv;
    st[idx] = (float)sv;
}

// ============================================================
// Split fp32 array into bf16 hi/lo
// ============================================================
__global__ void split_kernel(const float* __restrict__ src,
                             bf16* __restrict__ hi, bf16* __restrict__ lo,
                             int n) {
    int i = blockIdx.x * blockDim.x + threadIdx.x;
    if (i >= n) return;
    bf16 h, l;
    split_bf16(src[i], h, l);
    hi[i] = h;
    lo[i] = l;
}

// ============================================================
// 3xBF16 GEMM core: acc[m,n] += sum_k A[m,k]*B[n,k] (A,B pre-split)
// Tile BM x BN x K, double-buffered cp.async pipeline.
// ============================================================
__device__ __forceinline__ void gemm3_core(
    const bf16* __restrict__ Ahi, const bf16* __restrict__ Alo, int lda,
    const bf16* __restrict__ Bhi, const bf16* __restrict__ Blo, int ldb,
    int m0, int n0, int kSteps, float acc[4][4][4]) {
    extern __shared__ bf16 smem[];
    const int tid = threadIdx.x;
    const int wid = tid >> 5;
    const int lane = tid & 31;
    const int grp = lane >> 2;
    const int tig = lane & 3;
    const int wm = (wid & 1) * 64;
    const int wn = (wid >> 1) * 32;

    uint32_t smem_u32 = (uint32_t)__cvta_generic_to_shared(smem);

#pragma unroll
    for (int mt = 0; mt < 4; mt++)
#pragma unroll
        for (int nt = 0; nt < 4; nt++)
#pragma unroll
            for (int c = 0; c < 4; c++) acc[mt][nt][c] = 0.0f;

    const bf16* srcs[4];
    srcs[0] = Ahi + (size_t)m0 * lda;
    srcs[1] = Alo + (size_t)m0 * lda;
    srcs[2] = Bhi + (size_t)n0 * ldb;
    srcs[3] = Blo + (size_t)n0 * ldb;
    int ldsz[4] = {lda, lda, ldb, ldb};

    auto load_chunk = [&](int stage, int k0) {
#pragma unroll
        for (int i = 0; i < 8; i++) {
            const int op = i >> 1;
            const int q = tid + NTHREADS * (i & 1);  // 0..511 per operand
            const int r = q >> 2;                    // row 0..127
            const int c = (q & 3) * 8;               // bf16 col 0,8,16,24
            uint32_t dst = smem_u32 +
                (uint32_t)(((stage * 4 + op) * BUFB + r * SKB + c) * 2);
            const bf16* src = srcs[op] + (size_t)r * ldsz[op] + k0 + c;
            CP_ASYNC16(dst, src);
        }
        CP_COMMIT();
    };

    // prologue
    load_chunk(0, 0);
    CP_WAIT0();
    __syncthreads();

    for (int it = 0; it < kSteps; it++) {
        int s = it & 1;
        if (it + 1 < kSteps) load_chunk((it + 1) & 1, (it + 1) * BK);

        const uint32_t* As_h = (const uint32_t*)smem + (s * 4 + 0) * (BUFB / 2);
        const uint32_t* As_l = (const uint32_t*)smem + (s * 4 + 1) * (BUFB / 2);
        const uint32_t* Bs_h = (const uint32_t*)smem + (s * 4 + 2) * (BUFB / 2);
        const uint32_t* Bs_l = (const uint32_t*)smem + (s * 4 + 3) * (BUFB / 2);
        const int RW = SKB / 2;   // 20 words per row

#pragma unroll
        for (int kc = 0; kc < 2; kc++) {          // two k16 chunks per BK=32
            const int wb = kc * 8 + tig;
            uint32_t ah[4][4], al[4][4];
#pragma unroll
            for (int mt = 0; mt < 4; mt++) {
                int r0 = (wm + mt * 16 + grp) * RW;
                int r1 = r0 + 8 * RW;
                ah[mt][0] = As_h[r0 + wb];
                ah[mt][1] = As_h[r1 + wb];
                ah[mt][2] = As_h[r0 + wb + 4];
                ah[mt][3] = As_h[r1 + wb + 4];
                al[mt][0] = As_l[r0 + wb];
                al[mt][1] = As_l[r1 + wb];
                al[mt][2] = As_l[r0 + wb + 4];
                al[mt][3] = As_l[r1 + wb + 4];
            }
            uint32_t bh[4][2], bl[4][2];
#pragma unroll
            for (int nt = 0; nt < 4; nt++) {
                int rn = (wn + nt * 8 + grp) * RW;
                bh[nt][0] = Bs_h[rn + wb];
                bh[nt][1] = Bs_h[rn + wb + 4];
                bl[nt][0] = Bs_l[rn + wb];
                bl[nt][1] = Bs_l[rn + wb + 4];
            }
#pragma unroll
            for (int mt = 0; mt < 4; mt++)
#pragma unroll
                for (int nt = 0; nt < 4; nt++) {
                    MMA_BF16(acc[mt][nt], ah[mt], bh[nt]);
                    MMA_BF16(acc[mt][nt], ah[mt], bl[nt]);
                    MMA_BF16(acc[mt][nt], al[mt], bh[nt]);
                }
        }
        if (it + 1 < kSteps) CP_WAIT0();
        __syncthreads();
    }
}

// ============================================================
// QKV projection. mode 0: rope+split (Q/K). mode 1: transpose+split (V)
// grid = (DIM/BN, MTOT/BM)
// ============================================================
__global__ __launch_bounds__(NTHREADS, 2)
void qkv_mma_kernel(const bf16* __restrict__ Ahi, const bf16* __restrict__ Alo,
                    const bf16* __restrict__ Whi, const bf16* __restrict__ Wlo,
                    int mode,
                    bf16* __restrict__ Ohi, bf16* __restrict__ Olo,
                    const float* __restrict__ Ct, const float* __restrict__ St) {
    const int n0 = blockIdx.x * BN;
    const int m0 = blockIdx.y * BM;
    float acc[4][4][4];
    gemm3_core(Ahi, Alo, DIM, Whi, Wlo, DIM, m0, n0, DIM / BK, acc);

    const int tid = threadIdx.x;
    const int wid = tid >> 5;
    const int lane = tid & 31;
    const int grp = lane >> 2;
    const int tig = lane & 3;
    const int wm = (wid & 1) * 64;
    const int wn = (wid >> 1) * 32;

#pragma unroll
    for (int mt = 0; mt < 4; mt++)
#pragma unroll
        for (int nt = 0; nt < 4; nt++)
#pragma unroll
            for (int h = 0; h < 2; h++) {
                int row = m0 + wm + mt * 16 + grp + 8 * h;
                int colE = n0 + wn + nt * 8 + tig * 2;
                float e = acc[mt][nt][2 * h];
                float o = acc[mt][nt][2 * h + 1];
                if (mode == 0) {
                    int s = row & (SEQ - 1);
                    int j = colE >> 1;
                    float cth = Ct[(size_t)s * HALF_D + j];
                    float sth = St[(size_t)s * HALF_D + j];
                    float re = e * cth - o * sth;
                    float ro = e * sth + o * cth;
                    bf16 h1, l1, h2, l2;
                    split_bf16(re, h1, l1);
                    split_bf16(ro, h2, l2);
                    size_t p = (size_t)row * DIM + colE;
                    *(bf162*)(Ohi + p) = bf162{h1, h2};
                    *(bf162*)(Olo + p) = bf162{l1, l2};
                } else {
                    // transpose: Vt[b][col][s]
                    int b = row >> 12;
                    int s = row & (SEQ - 1);
                    bf16 h1, l1, h2, l2;
                    split_bf16(e, h1, l1);
                    split_bf16(o, h2, l2);
                    size_t p0 = ((size_t)b * DIM + colE) * SEQ + s;
                    size_t p1 = ((size_t)b * DIM + colE + 1) * SEQ + s;
                    Ohi[p0] = h1; Olo[p0] = l1;
                    Ohi[p1] = h2; Olo[p1] = l2;
                }
            }
}

// ============================================================
// Scores: P = (Q K^T)/32, lower-triangle tiles, fp32 output.
// grid = (SEQ/BN, SEQ/BM, BATCH)
// ============================================================
__global__ __launch_bounds__(NTHREADS, 2)
void scores_mma_kernel(const bf16* __restrict__ Qhi, const bf16* __restrict__ Qlo,
                       const bf16* __restrict__ Khi, const bf16* __restrict__ Klo,
                       float* __restrict__ Ps) {
    const int n0 = blockIdx.x * BN;
    const int m0 = blockIdx.y * BM;
    if (n0 > m0) return;
    const int b = blockIdx.z;
    const size_t boff = (size_t)b * SEQ * DIM;

    float acc[4][4][4];
    gemm3_core(Qhi + boff, Qlo + boff, DIM, Khi + boff, Klo + boff, DIM,
               m0, n0, DIM / BK, acc);

    const int tid = threadIdx.x;
    const int wid = tid >> 5;
    const int lane = tid & 31;
    const int grp = lane >> 2;
    const int tig = lane & 3;
    const int wm = (wid & 1) * 64;
    const int wn = (wid >> 1) * 32;
    const float scale = 1.0f / 32.0f;

    float* Pb = Ps + (size_t)b * SEQ * SEQ;
#pragma unroll
    for (int mt = 0; mt < 4; mt++)
#pragma unroll
        for (int nt = 0; nt < 4; nt++)
#pragma unroll
            for (int h = 0; h < 2; h++) {
                int row = m0 + wm + mt * 16 + grp + 8 * h;
                int col = n0 + wn + nt * 8 + tig * 2;
                float2 v;
                v.x = acc[mt][nt][2 * h] * scale;
                v.y = acc[mt][nt][2 * h + 1] * scale;
                *(float2*)(Pb + (size_t)row * SEQ + col) = v;
            }
}

// ============================================================
// Causal softmax: fp32 scores in, bf16 hi/lo probs out (+zero pad)
// ============================================================
__global__ __launch_bounds__(NTHREADS)
void softmax_kernel(float* __restrict__ Ps,
                    bf16* __restrict__ Pbh, bf16* __restrict__ Pbl) {
    __shared__ float red[NTHREADS / 32];
    const int rowg = blockIdx.x;
    const int b = rowg >> 12;
    const int i = rowg & (SEQ - 1);
    float* p = Ps + ((size_t)b * SEQ + i) * SEQ;
    bf16* ph = Pbh + ((size_t)b * SEQ + i) * SEQ;
    bf16* pl = Pbl + ((size_t)b * SEQ + i) * SEQ;
    const int L = i + 1;
    const int tid = threadIdx.x;
    const int lane = tid & 31;
    const int wrp = tid >> 5;

    float m = -3.0e38f;
    for (int j = tid; j < L; j += NTHREADS) m = fmaxf(m, p[j]);
#pragma unroll
    for (int o = 16; o > 0; o >>= 1) m = fmaxf(m, __shfl_xor_sync(~0u, m, o));
    if (lane == 0) red[wrp] = m;
    __syncthreads();
    m = red[0];
#pragma unroll
    for (int w = 1; w < NTHREADS / 32; w++) m = fmaxf(m, red[w]);

    float sum = 0.0f;
    for (int j = tid; j < L; j += NTHREADS) {
        float e = expf(p[j] - m);
        p[j] = e;
        sum += e;
    }
#pragma unroll
    for (int o = 16; o > 0; o >>= 1) sum += __shfl_xor_sync(~0u, sum, o);
    __syncthreads();
    if (lane == 0) red[wrp] = sum;
    __syncthreads();
    sum = 0.0f;
#pragma unroll
    for (int w = 0; w < NTHREADS / 32; w++) sum += red[w];

    const float inv = 1.0f / sum;
    for (int j = tid; j < L; j += NTHREADS) {
        bf16 h, l;
        split_bf16(p[j] * inv, h, l);
        ph[j] = h;
        pl[j] = l;
    }
    const int bound = (i & ~127) + 128;
    for (int j = L + tid; j < bound; j += NTHREADS) {
        ph[j] = __float2bfloat16(0.0f);
        pl[j] = __float2bfloat16(0.0f);
    }
}

// ============================================================
// PV: O = P @ V using Vt (K-major), causal-truncated k-loop.
// grid = (DIM/BN, SEQ/BM, BATCH)
// ============================================================
__global__ __launch_bounds__(NTHREADS, 2)
void pv_mma_kernel(const bf16* __restrict__ Pbh, const bf16* __restrict__ Pbl,
                   const bf16* __restrict__ Vthi, const bf16* __restrict__ Vtlo,
                   float* __restrict__ O) {
    const int n0 = blockIdx.x * BN;
    const int m0 = blockIdx.y * BM;
    const int b = blockIdx.z;

    const bf16* Ah = Pbh + (size_t)b * SEQ * SEQ;
    const bf16* Al = Pbl + (size_t)b * SEQ * SEQ;
    const bf16* Bh = Vthi + (size_t)b * DIM * SEQ;
    const bf16* Bl = Vtlo + (size_t)b * DIM * SEQ;

    float acc[4][4][4];
    gemm3_core(Ah, Al, SEQ, Bh, Bl, SEQ, m0, n0, (m0 + BM) / BK, acc);

    const int tid = threadIdx.x;
    const int wid = tid >> 5;
    const int lane = tid & 31;
    const int grp = lane >> 2;
    const int tig = lane & 3;
    const int wm = (wid & 1) * 64;
    const int wn = (wid >> 1) * 32;

#pragma unroll
    for (int mt = 0; mt < 4; mt++)
#pragma unroll
        for (int nt = 0; nt < 4; nt++)
#pragma unroll
            for (int h = 0; h < 2; h++) {
                int row = m0 + wm + mt * 16 + grp + 8 * h;
                int col = n0 + wn + nt * 8 + tig * 2;
                float2 v;
                v.x = acc[mt][nt][2 * h];
                v.y = acc[mt][nt][2 * h + 1];
                *(float2*)(O + ((size_t)b * SEQ + row) * DIM + col) = v;
            }
}

// ============================================================
// Launch
// ============================================================
extern "C" void kernel_launch(void* const* d_in, const int* in_sizes, int n_in,
                              void* d_out, int out_size) {
    const float* x  = (const float*)d_in[0];
    const float* Wq = (const float*)d_in[1];
    const float* Wk = (const float*)d_in[2];
    const float* Wv = (const float*)d_in[3];
    float* out = (float*)d_out;

    bf16 *xh, *xl, *Wh, *Wl, *Qh, *Ql, *Kh, *Kl, *Vth, *Vtl, *Pbh, *Pbl;
    float *Psf, *Cp, *Sp;
    cudaGetSymbolAddress((void**)&xh, g_xhi);
    cudaGetSymbolAddress((void**)&xl, g_xlo);
    cudaGetSymbolAddress((void**)&Wh, g_Whi);
    cudaGetSymbolAddress((void**)&Wl, g_Wlo);
    cudaGetSymbolAddress((void**)&Qh, g_Qhi);
    cudaGetSymbolAddress((void**)&Ql, g_Qlo);
    cudaGetSymbolAddress((void**)&Kh, g_Khi);
    cudaGetSymbolAddress((void**)&Kl, g_Klo);
    cudaGetSymbolAddress((void**)&Vth, g_Vthi);
    cudaGetSymbolAddress((void**)&Vtl, g_Vtlo);
    cudaGetSymbolAddress((void**)&Psf, g_Ps);
    cudaGetSymbolAddress((void**)&Pbh, g_Pbh);
    cudaGetSymbolAddress((void**)&Pbl, g_Pbl);
    cudaGetSymbolAddress((void**)&Cp, g_cos);
    cudaGetSymbolAddress((void**)&Sp, g_sin);

    cudaFuncSetAttribute(qkv_mma_kernel,    cudaFuncAttributeMaxDynamicSharedMemorySize, SMEM_BYTES);
    cudaFuncSetAttribute(scores_mma_kernel, cudaFuncAttributeMaxDynamicSharedMemorySize, SMEM_BYTES);
    cudaFuncSetAttribute(pv_mma_kernel,     cudaFuncAttributeMaxDynamicSharedMemorySize, SMEM_BYTES);

    // 1) trig tables
    {
        int total = SEQ * HALF_D;
        trig_table_kernel<<<(total + 255) / 256, 256>>>(Cp, Sp);
    }

    // 2) split inputs to bf16 hi/lo
    {
        int nx = MTOT * DIM;
        split_kernel<<<(nx + 255) / 256, 256>>>(x, xh, xl, nx);
        int nw = DIM * DIM;
        split_kernel<<<(nw + 255) / 256, 256>>>(Wq, Wh + 0 * (size_t)nw, Wl + 0 * (size_t)nw, nw);
        split_kernel<<<(nw + 255) / 256, 256>>>(Wk, Wh + 1 * (size_t)nw, Wl + 1 * (size_t)nw, nw);
        split_kernel<<<(nw + 255) / 256, 256>>>(Wv, Wh + 2 * (size_t)nw, Wl + 2 * (size_t)nw, nw);
    }

    // 3) projections (rope fused for Q,K; transpose fused for V)
    {
        dim3 grid(DIM / BN, MTOT / BM);   // (8, 128)
        size_t nw = (size_t)DIM * DIM;
        qkv_mma_kernel<<<grid, NTHREADS, SMEM_BYTES>>>(xh, xl, Wh + 0 * nw, Wl + 0 * nw, 0, Qh, Ql, Cp, Sp);
        qkv_mma_kernel<<<grid, NTHREADS, SMEM_BYTES>>>(xh, xl, Wh + 1 * nw, Wl + 1 * nw, 0, Kh, Kl, Cp, Sp);
        qkv_mma_kernel<<<grid, NTHREADS, SMEM_BYTES>>>(xh, xl, Wh + 2 * nw, Wl + 2 * nw, 1, Vth, Vtl, Cp, Sp);
    }

    // 4) causal scores (fp32 output)
    {
        dim3 grid(SEQ / BN, SEQ / BM, BATCH);
        scores_mma_kernel<<<grid, NTHREADS, SMEM_BYTES>>>(Qh, Ql, Kh, Kl, Psf);
    }

    // 5) softmax (fp32 in, split bf16 out + pad)
    softmax_kernel<<<BATCH * SEQ, NTHREADS>>>(Psf, Pbh, Pbl);

    // 6) O = P @ V
    {
        dim3 grid(DIM / BN, SEQ / BM, BATCH);
        pv_mma_kernel<<<grid, NTHREADS, SMEM_BYTES>>>(Pbh, Pbl, Vth, Vtl, out);
    }
}

// round 9
// speedup vs baseline: 2.6365x; 1.0744x over previous
#include <cuda_runtime.h>
#include <cuda_bf16.h>
#include <math.h>
#include <stdint.h>

typedef __nv_bfloat16 bf16;
typedef __nv_bfloat162 bf162;

// Problem constants
#define BATCH 4
#define SEQ   4096
#define DIM   1024
#define MTOT  (BATCH * SEQ)     // 16384
#define HALF_D (DIM / 2)        // 512

// GEMM tiling
#define BM 128
#define BN 128
#define BK 32
#define NTHREADS 256
#define SKB 40                          // padded smem row stride (bf16 elems) = 80 bytes
#define BUFB (BM * SKB)                 // 5120 bf16 per operand buffer
#define SMEM_BYTES (2 * 4 * BUFB * 2)   // 2 stages x 4 operands x bf16 = 81920 B

// -------- device scratch (no cudaMalloc allowed) --------
__device__ bf16 g_xhi[(size_t)MTOT * DIM];
__device__ bf16 g_xlo[(size_t)MTOT * DIM];
__device__ bf16 g_Whi[(size_t)3 * DIM * DIM];
__device__ bf16 g_Wlo[(size_t)3 * DIM * DIM];
__device__ bf16 g_Qhi[(size_t)MTOT * DIM];
__device__ bf16 g_Qlo[(size_t)MTOT * DIM];
__device__ bf16 g_Khi[(size_t)MTOT * DIM];
__device__ bf16 g_Klo[(size_t)MTOT * DIM];
__device__ bf16 g_Vthi[(size_t)MTOT * DIM];   // [b][dim][seq]
__device__ bf16 g_Vtlo[(size_t)MTOT * DIM];
__device__ float g_Ps[(size_t)BATCH * SEQ * SEQ];   // fp32 scores
__device__ bf16 g_Pbh[(size_t)BATCH * SEQ * SEQ];   // split probs for PV
__device__ bf16 g_Pbl[(size_t)BATCH * SEQ * SEQ];
__device__ float g_cos[(size_t)SEQ * HALF_D];
__device__ float g_sin[(size_t)SEQ * HALF_D];

// ============================================================
// helpers
// ============================================================
__device__ __forceinline__ void split_bf16(float x, bf16& hi, bf16& lo) {
    hi = __float2bfloat16_rn(x);
    lo = __float2bfloat16_rn(x - __bfloat162float(hi));
}

#define MMA_BF16(D, A, B)                                                   \
    asm volatile(                                                           \
        "mma.sync.aligned.m16n8k16.row.col.f32.bf16.bf16.f32 "              \
        "{%0,%1,%2,%3}, {%4,%5,%6,%7}, {%8,%9}, {%0,%1,%2,%3};"             \
        : "+f"((D)[0]), "+f"((D)[1]), "+f"((D)[2]), "+f"((D)[3])            \
        : "r"((A)[0]), "r"((A)[1]), "r"((A)[2]), "r"((A)[3]),               \
          "r"((B)[0]), "r"((B)[1]))

#define LDSM_X4(R, addr)                                                    \
    asm volatile(                                                           \
        "ldmatrix.sync.aligned.m8n8.x4.shared.b16 {%0,%1,%2,%3}, [%4];"     \
        : "=r"((R)[0]), "=r"((R)[1]), "=r"((R)[2]), "=r"((R)[3])            \
        : "r"(addr))

#define CP_ASYNC16(dst, src)                                                \
    asm volatile("cp.async.cg.shared.global [%0], [%1], 16;"                \
                 :: "r"(dst), "l"(src))
#define CP_COMMIT() asm volatile("cp.async.commit_group;")
#define CP_WAIT0()  asm volatile("cp.async.wait_group 0;")

// ============================================================
// RoPE cos/sin table (double precision generation)
// ============================================================
__global__ void trig_table_kernel(float* ct, float* st) {
    int idx = blockIdx.x * blockDim.x + threadIdx.x;
    if (idx >= SEQ * HALF_D) return;
    int s = idx / HALF_D;
    int j = idx % HALF_D;
    double inv = exp(-((double)(2 * j) / (double)DIM) * 9.210340371976184);
    double ang = (double)s * inv;
    double sv, cv;
    sincos(ang, &sv, &cv);
    ct[idx] = (float)cv;
    st[idx] = (float)sv;
}

// ============================================================
// Split fp32 array into bf16 hi/lo
// ============================================================
__global__ void split_kernel(const float* __restrict__ src,
                             bf16* __restrict__ hi, bf16* __restrict__ lo,
                             int n) {
    int i = blockIdx.x * blockDim.x + threadIdx.x;
    if (i >= n) return;
    bf16 h, l;
    split_bf16(src[i], h, l);
    hi[i] = h;
    lo[i] = l;
}

// ============================================================
// 3xBF16 GEMM core: acc[m,n] += sum_k A[m,k]*B[n,k] (A,B pre-split)
// Tile BM x BN x K, double-buffered cp.async pipeline, ldmatrix frags.
// ============================================================
__device__ __forceinline__ void gemm3_core(
    const bf16* __restrict__ Ahi, const bf16* __restrict__ Alo, int lda,
    const bf16* __restrict__ Bhi, const bf16* __restrict__ Blo, int ldb,
    int m0, int n0, int kSteps, float acc[4][4][4]) {
    extern __shared__ bf16 smem[];
    const int tid = threadIdx.x;
    const int wid = tid >> 5;
    const int lane = tid & 31;
    const int wm = (wid & 1) * 64;
    const int wn = (wid >> 1) * 32;

    // ldmatrix per-lane addressing
    const uint32_t a_row  = lane & 15;
    const uint32_t a_koff = (uint32_t)((lane >> 4) << 3);          // 0 or 8 elems
    const uint32_t b_row  = (uint32_t)((lane & 7) + ((lane >> 4) << 3));
    const uint32_t b_koff = (uint32_t)(((lane >> 3) & 1) << 3);    // 0 or 8 elems

    uint32_t smem_u32 = (uint32_t)__cvta_generic_to_shared(smem);

#pragma unroll
    for (int mt = 0; mt < 4; mt++)
#pragma unroll
        for (int nt = 0; nt < 4; nt++)
#pragma unroll
            for (int c = 0; c < 4; c++) acc[mt][nt][c] = 0.0f;

    const bf16* srcs[4];
    srcs[0] = Ahi + (size_t)m0 * lda;
    srcs[1] = Alo + (size_t)m0 * lda;
    srcs[2] = Bhi + (size_t)n0 * ldb;
    srcs[3] = Blo + (size_t)n0 * ldb;
    int ldsz[4] = {lda, lda, ldb, ldb};

    auto load_chunk = [&](int stage, int k0) {
#pragma unroll
        for (int i = 0; i < 8; i++) {
            const int op = i >> 1;
            const int q = tid + NTHREADS * (i & 1);  // 0..511 per operand
            const int r = q >> 2;                    // row 0..127
            const int c = (q & 3) * 8;               // bf16 col 0,8,16,24
            uint32_t dst = smem_u32 +
                (uint32_t)(((stage * 4 + op) * BUFB + r * SKB + c) * 2);
            const bf16* src = srcs[op] + (size_t)r * ldsz[op] + k0 + c;
            CP_ASYNC16(dst, src);
        }
        CP_COMMIT();
    };

    // prologue
    load_chunk(0, 0);
    CP_WAIT0();
    __syncthreads();

    for (int it = 0; it < kSteps; it++) {
        int s = it & 1;
        if (it + 1 < kSteps) load_chunk((it + 1) & 1, (it + 1) * BK);

        const uint32_t stA_h = smem_u32 + (uint32_t)((s * 4 + 0) * BUFB * 2);
        const uint32_t stA_l = smem_u32 + (uint32_t)((s * 4 + 1) * BUFB * 2);
        const uint32_t stB_h = smem_u32 + (uint32_t)((s * 4 + 2) * BUFB * 2);
        const uint32_t stB_l = smem_u32 + (uint32_t)((s * 4 + 3) * BUFB * 2);

#pragma unroll
        for (int kc = 0; kc < 2; kc++) {          // two k16 chunks per BK=32
            const uint32_t kbase = (uint32_t)(kc * 16);
            uint32_t ah[4][4], al[4][4], bh[4][2], bl[4][2];
#pragma unroll
            for (int mt = 0; mt < 4; mt++) {
                uint32_t ra = (uint32_t)(((wm + mt * 16 + a_row) * SKB + kbase + a_koff) * 2);
                LDSM_X4(ah[mt], stA_h + ra);
                LDSM_X4(al[mt], stA_l + ra);
            }
#pragma unroll
            for (int p = 0; p < 2; p++) {         // nt pairs (2p, 2p+1)
                uint32_t rb = (uint32_t)(((wn + p * 16 + b_row) * SKB + kbase + b_koff) * 2);
                uint32_t t[4];
                LDSM_X4(t, stB_h + rb);
                bh[2 * p][0] = t[0]; bh[2 * p][1] = t[1];
                bh[2 * p + 1][0] = t[2]; bh[2 * p + 1][1] = t[3];
                LDSM_X4(t, stB_l + rb);
                bl[2 * p][0] = t[0]; bl[2 * p][1] = t[1];
                bl[2 * p + 1][0] = t[2]; bl[2 * p + 1][1] = t[3];
            }
#pragma unroll
            for (int mt = 0; mt < 4; mt++)
#pragma unroll
                for (int nt = 0; nt < 4; nt++) {
                    MMA_BF16(acc[mt][nt], ah[mt], bh[nt]);
                    MMA_BF16(acc[mt][nt], ah[mt], bl[nt]);
                    MMA_BF16(acc[mt][nt], al[mt], bh[nt]);
                }
        }
        if (it + 1 < kSteps) CP_WAIT0();
        __syncthreads();
    }
}

// ============================================================
// QKV projection. mode 0: rope+split (Q/K). mode 1: transpose+split (V)
// grid = (DIM/BN, MTOT/BM)
// ============================================================
__global__ __launch_bounds__(NTHREADS, 2)
void qkv_mma_kernel(const bf16* __restrict__ Ahi, const bf16* __restrict__ Alo,
                    const bf16* __restrict__ Whi, const bf16* __restrict__ Wlo,
                    int mode,
                    bf16* __restrict__ Ohi, bf16* __restrict__ Olo,
                    const float* __restrict__ Ct, const float* __restrict__ St) {
    const int n0 = blockIdx.x * BN;
    const int m0 = blockIdx.y * BM;
    float acc[4][4][4];
    gemm3_core(Ahi, Alo, DIM, Whi, Wlo, DIM, m0, n0, DIM / BK, acc);

    const int tid = threadIdx.x;
    const int wid = tid >> 5;
    const int lane = tid & 31;
    const int grp = lane >> 2;
    const int tig = lane & 3;
    const int wm = (wid & 1) * 64;
    const int wn = (wid >> 1) * 32;

#pragma unroll
    for (int mt = 0; mt < 4; mt++)
#pragma unroll
        for (int nt = 0; nt < 4; nt++)
#pragma unroll
            for (int h = 0; h < 2; h++) {
                int row = m0 + wm + mt * 16 + grp + 8 * h;
                int colE = n0 + wn + nt * 8 + tig * 2;
                float e = acc[mt][nt][2 * h];
                float o = acc[mt][nt][2 * h + 1];
                if (mode == 0) {
                    int s = row & (SEQ - 1);
                    int j = colE >> 1;
                    float cth = Ct[(size_t)s * HALF_D + j];
                    float sth = St[(size_t)s * HALF_D + j];
                    float re = e * cth - o * sth;
                    float ro = e * sth + o * cth;
                    bf16 h1, l1, h2, l2;
                    split_bf16(re, h1, l1);
                    split_bf16(ro, h2, l2);
                    size_t p = (size_t)row * DIM + colE;
                    *(bf162*)(Ohi + p) = bf162{h1, h2};
                    *(bf162*)(Olo + p) = bf162{l1, l2};
                } else {
                    // transpose: Vt[b][col][s]
                    int b = row >> 12;
                    int s = row & (SEQ - 1);
                    bf16 h1, l1, h2, l2;
                    split_bf16(e, h1, l1);
                    split_bf16(o, h2, l2);
                    size_t p0 = ((size_t)b * DIM + colE) * SEQ + s;
                    size_t p1 = ((size_t)b * DIM + colE + 1) * SEQ + s;
                    Ohi[p0] = h1; Olo[p0] = l1;
                    Ohi[p1] = h2; Olo[p1] = l2;
                }
            }
}

// ============================================================
// Scores: P = (Q K^T)/32, lower-triangle tiles, fp32 output.
// grid = (SEQ/BN, SEQ/BM, BATCH)
// ============================================================
__global__ __launch_bounds__(NTHREADS, 2)
void scores_mma_kernel(const bf16* __restrict__ Qhi, const bf16* __restrict__ Qlo,
                       const bf16* __restrict__ Khi, const bf16* __restrict__ Klo,
                       float* __restrict__ Ps) {
    const int n0 = blockIdx.x * BN;
    const int m0 = blockIdx.y * BM;
    if (n0 > m0) return;
    const int b = blockIdx.z;
    const size_t boff = (size_t)b * SEQ * DIM;

    float acc[4][4][4];
    gemm3_core(Qhi + boff, Qlo + boff, DIM, Khi + boff, Klo + boff, DIM,
               m0, n0, DIM / BK, acc);

    const int tid = threadIdx.x;
    const int wid = tid >> 5;
    const int lane = tid & 31;
    const int grp = lane >> 2;
    const int tig = lane & 3;
    const int wm = (wid & 1) * 64;
    const int wn = (wid >> 1) * 32;
    const float scale = 1.0f / 32.0f;

    float* Pb = Ps + (size_t)b * SEQ * SEQ;
#pragma unroll
    for (int mt = 0; mt < 4; mt++)
#pragma unroll
        for (int nt = 0; nt < 4; nt++)
#pragma unroll
            for (int h = 0; h < 2; h++) {
                int row = m0 + wm + mt * 16 + grp + 8 * h;
                int col = n0 + wn + nt * 8 + tig * 2;
                float2 v;
                v.x = acc[mt][nt][2 * h] * scale;
                v.y = acc[mt][nt][2 * h + 1] * scale;
                *(float2*)(Pb + (size_t)row * SEQ + col) = v;
            }
}

// ============================================================
// Causal softmax: fp32 scores in, bf16 hi/lo probs out (+zero pad)
// ============================================================
__global__ __launch_bounds__(NTHREADS)
void softmax_kernel(float* __restrict__ Ps,
                    bf16* __restrict__ Pbh, bf16* __restrict__ Pbl) {
    __shared__ float red[NTHREADS / 32];
    const int rowg = blockIdx.x;
    const int b = rowg >> 12;
    const int i = rowg & (SEQ - 1);
    float* p = Ps + ((size_t)b * SEQ + i) * SEQ;
    bf16* ph = Pbh + ((size_t)b * SEQ + i) * SEQ;
    bf16* pl = Pbl + ((size_t)b * SEQ + i) * SEQ;
    const int L = i + 1;
    const int tid = threadIdx.x;
    const int lane = tid & 31;
    const int wrp = tid >> 5;

    float m = -3.0e38f;
    for (int j = tid; j < L; j += NTHREADS) m = fmaxf(m, p[j]);
#pragma unroll
    for (int o = 16; o > 0; o >>= 1) m = fmaxf(m, __shfl_xor_sync(~0u, m, o));
    if (lane == 0) red[wrp] = m;
    __syncthreads();
    m = red[0];
#pragma unroll
    for (int w = 1; w < NTHREADS / 32; w++) m = fmaxf(m, red[w]);

    float sum = 0.0f;
    for (int j = tid; j < L; j += NTHREADS) {
        float e = expf(p[j] - m);
        p[j] = e;
        sum += e;
    }
#pragma unroll
    for (int o = 16; o > 0; o >>= 1) sum += __shfl_xor_sync(~0u, sum, o);
    __syncthreads();
    if (lane == 0) red[wrp] = sum;
    __syncthreads();
    sum = 0.0f;
#pragma unroll
    for (int w = 0; w < NTHREADS / 32; w++) sum += red[w];

    const float inv = 1.0f / sum;
    for (int j = tid; j < L; j += NTHREADS) {
        bf16 h, l;
        split_bf16(p[j] * inv, h, l);
        ph[j] = h;
        pl[j] = l;
    }
    const int bound = (i & ~127) + 128;
    for (int j = L + tid; j < bound; j += NTHREADS) {
        ph[j] = __float2bfloat16(0.0f);
        pl[j] = __float2bfloat16(0.0f);
    }
}

// ============================================================
// PV: O = P @ V using Vt (K-major), causal-truncated k-loop.
// grid = (DIM/BN, SEQ/BM, BATCH)
// ============================================================
__global__ __launch_bounds__(NTHREADS, 2)
void pv_mma_kernel(const bf16* __restrict__ Pbh, const bf16* __restrict__ Pbl,
                   const bf16* __restrict__ Vthi, const bf16* __restrict__ Vtlo,
                   float* __restrict__ O) {
    const int n0 = blockIdx.x * BN;
    const int m0 = blockIdx.y * BM;
    const int b = blockIdx.z;

    const bf16* Ah = Pbh + (size_t)b * SEQ * SEQ;
    const bf16* Al = Pbl + (size_t)b * SEQ * SEQ;
    const bf16* Bh = Vthi + (size_t)b * DIM * SEQ;
    const bf16* Bl = Vtlo + (size_t)b * DIM * SEQ;

    float acc[4][4][4];
    gemm3_core(Ah, Al, SEQ, Bh, Bl, SEQ, m0, n0, (m0 + BM) / BK, acc);

    const int tid = threadIdx.x;
    const int wid = tid >> 5;
    const int lane = tid & 31;
    const int grp = lane >> 2;
    const int tig = lane & 3;
    const int wm = (wid & 1) * 64;
    const int wn = (wid >> 1) * 32;

#pragma unroll
    for (int mt = 0; mt < 4; mt++)
#pragma unroll
        for (int nt = 0; nt < 4; nt++)
#pragma unroll
            for (int h = 0; h < 2; h++) {
                int row = m0 + wm + mt * 16 + grp + 8 * h;
                int col = n0 + wn + nt * 8 + tig * 2;
                float2 v;
                v.x = acc[mt][nt][2 * h];
                v.y = acc[mt][nt][2 * h + 1];
                *(float2*)(O + ((size_t)b * SEQ + row) * DIM + col) = v;
            }
}

// ============================================================
// Launch
// ============================================================
extern "C" void kernel_launch(void* const* d_in, const int* in_sizes, int n_in,
                              void* d_out, int out_size) {
    const float* x  = (const float*)d_in[0];
    const float* Wq = (const float*)d_in[1];
    const float* Wk = (const float*)d_in[2];
    const float* Wv = (const float*)d_in[3];
    float* out = (float*)d_out;

    bf16 *xh, *xl, *Wh, *Wl, *Qh, *Ql, *Kh, *Kl, *Vth, *Vtl, *Pbh, *Pbl;
    float *Psf, *Cp, *Sp;
    cudaGetSymbolAddress((void**)&xh, g_xhi);
    cudaGetSymbolAddress((void**)&xl, g_xlo);
    cudaGetSymbolAddress((void**)&Wh, g_Whi);
    cudaGetSymbolAddress((void**)&Wl, g_Wlo);
    cudaGetSymbolAddress((void**)&Qh, g_Qhi);
    cudaGetSymbolAddress((void**)&Ql, g_Qlo);
    cudaGetSymbolAddress((void**)&Kh, g_Khi);
    cudaGetSymbolAddress((void**)&Kl, g_Klo);
    cudaGetSymbolAddress((void**)&Vth, g_Vthi);
    cudaGetSymbolAddress((void**)&Vtl, g_Vtlo);
    cudaGetSymbolAddress((void**)&Psf, g_Ps);
    cudaGetSymbolAddress((void**)&Pbh, g_Pbh);
    cudaGetSymbolAddress((void**)&Pbl, g_Pbl);
    cudaGetSymbolAddress((void**)&Cp, g_cos);
    cudaGetSymbolAddress((void**)&Sp, g_sin);

    cudaFuncSetAttribute(qkv_mma_kernel,    cudaFuncAttributeMaxDynamicSharedMemorySize, SMEM_BYTES);
    cudaFuncSetAttribute(scores_mma_kernel, cudaFuncAttributeMaxDynamicSharedMemorySize, SMEM_BYTES);
    cudaFuncSetAttribute(pv_mma_kernel,     cudaFuncAttributeMaxDynamicSharedMemorySize, SMEM_BYTES);

    // 1) trig tables
    {
        int total = SEQ * HALF_D;
        trig_table_kernel<<<(total + 255) / 256, 256>>>(Cp, Sp);
    }

    // 2) split inputs to bf16 hi/lo
    {
        int nx = MTOT * DIM;
        split_kernel<<<(nx + 255) / 256, 256>>>(x, xh, xl, nx);
        int nw = DIM * DIM;
        split_kernel<<<(nw + 255) / 256, 256>>>(Wq, Wh + 0 * (size_t)nw, Wl + 0 * (size_t)nw, nw);
        split_kernel<<<(nw + 255) / 256, 256>>>(Wk, Wh + 1 * (size_t)nw, Wl + 1 * (size_t)nw, nw);
        split_kernel<<<(nw + 255) / 256, 256>>>(Wv, Wh + 2 * (size_t)nw, Wl + 2 * (size_t)nw, nw);
    }

    // 3) projections (rope fused for Q,K; transpose fused for V)
    {
        dim3 grid(DIM / BN, MTOT / BM);   // (8, 128)
        size_t nw = (size_t)DIM * DIM;
        qkv_mma_kernel<<<grid, NTHREADS, SMEM_BYTES>>>(xh, xl, Wh + 0 * nw, Wl + 0 * nw, 0, Qh, Ql, Cp, Sp);
        qkv_mma_kernel<<<grid, NTHREADS, SMEM_BYTES>>>(xh, xl, Wh + 1 * nw, Wl + 1 * nw, 0, Kh, Kl, Cp, Sp);
        qkv_mma_kernel<<<grid, NTHREADS, SMEM_BYTES>>>(xh, xl, Wh + 2 * nw, Wl + 2 * nw, 1, Vth, Vtl, Cp, Sp);
    }

    // 4) causal scores (fp32 output)
    {
        dim3 grid(SEQ / BN, SEQ / BM, BATCH);
        scores_mma_kernel<<<grid, NTHREADS, SMEM_BYTES>>>(Qh, Ql, Kh, Kl, Psf);
    }

    // 5) softmax (fp32 in, split bf16 out + pad)
    softmax_kernel<<<BATCH * SEQ, NTHREADS>>>(Psf, Pbh, Pbl);

    // 6) O = P @ V
    {
        dim3 grid(DIM / BN, SEQ / BM, BATCH);
        pv_mma_kernel<<<grid, NTHREADS, SMEM_BYTES>>>(Pbh, Pbl, Vth, Vtl, out);
    }
}

// round 10
// speedup vs baseline: 2.7174x; 1.0307x over previous
#include <cuda_runtime.h>
#include <cuda_bf16.h>
#include <math.h>
#include <stdint.h>

typedef __nv_bfloat16 bf16;
typedef __nv_bfloat162 bf162;

// Problem constants
#define BATCH 4
#define SEQ   4096
#define DIM   1024
#define MTOT  (BATCH * SEQ)     // 16384
#define HALF_D (DIM / 2)        // 512

// GEMM tiling
#define BM 128
#define BN 128
#define BK 32
#define NTHREADS 256
#define SKB 40                          // padded smem row stride (bf16 elems) = 80 bytes
#define BUFB (BM * SKB)                 // 5120 bf16 per operand buffer
#define SMEM_BYTES (2 * 4 * BUFB * 2)   // 2 stages x 4 operands x bf16 = 81920 B

// -------- device scratch (no cudaMalloc allowed) --------
__device__ bf16 g_xhi[(size_t)MTOT * DIM];
__device__ bf16 g_xlo[(size_t)MTOT * DIM];
__device__ bf16 g_Whi[(size_t)3 * DIM * DIM];
__device__ bf16 g_Wlo[(size_t)3 * DIM * DIM];
__device__ bf16 g_Qhi[(size_t)MTOT * DIM];
__device__ bf16 g_Qlo[(size_t)MTOT * DIM];
__device__ bf16 g_Khi[(size_t)MTOT * DIM];
__device__ bf16 g_Klo[(size_t)MTOT * DIM];
__device__ bf16 g_Vthi[(size_t)MTOT * DIM];   // [b][dim][seq]
__device__ bf16 g_Vtlo[(size_t)MTOT * DIM];
__device__ bf16 g_Pbh[(size_t)BATCH * SEQ * SEQ];   // unnormalized exp(scores), split
__device__ bf16 g_Pbl[(size_t)BATCH * SEQ * SEQ];
__device__ float g_rsum[(size_t)MTOT];              // per-row sum of exp
__device__ float g_cos[(size_t)SEQ * HALF_D];
__device__ float g_sin[(size_t)SEQ * HALF_D];

// ============================================================
// helpers
// ============================================================
__device__ __forceinline__ void split_bf16(float x, bf16& hi, bf16& lo) {
    hi = __float2bfloat16_rn(x);
    lo = __float2bfloat16_rn(x - __bfloat162float(hi));
}

#define MMA_BF16(D, A, B)                                                   \
    asm volatile(                                                           \
        "mma.sync.aligned.m16n8k16.row.col.f32.bf16.bf16.f32 "              \
        "{%0,%1,%2,%3}, {%4,%5,%6,%7}, {%8,%9}, {%0,%1,%2,%3};"             \
        : "+f"((D)[0]), "+f"((D)[1]), "+f"((D)[2]), "+f"((D)[3])            \
        : "r"((A)[0]), "r"((A)[1]), "r"((A)[2]), "r"((A)[3]),               \
          "r"((B)[0]), "r"((B)[1]))

#define LDSM_X4(R, addr)                                                    \
    asm volatile(                                                           \
        "ldmatrix.sync.aligned.m8n8.x4.shared.b16 {%0,%1,%2,%3}, [%4];"     \
        : "=r"((R)[0]), "=r"((R)[1]), "=r"((R)[2]), "=r"((R)[3])            \
        : "r"(addr))

#define CP_ASYNC16(dst, src)                                                \
    asm volatile("cp.async.cg.shared.global [%0], [%1], 16;"                \
                 :: "r"(dst), "l"(src))
#define CP_COMMIT() asm volatile("cp.async.commit_group;")
#define CP_WAIT0()  asm volatile("cp.async.wait_group 0;")

// ============================================================
// RoPE cos/sin table (double precision generation)
// ============================================================
__global__ void trig_table_kernel(float* ct, float* st) {
    int idx = blockIdx.x * blockDim.x + threadIdx.x;
    if (idx >= SEQ * HALF_D) return;
    int s = idx / HALF_D;
    int j = idx % HALF_D;
    double inv = exp(-((double)(2 * j) / (double)DIM) * 9.210340371976184);
    double ang = (double)s * inv;
    double sv, cv;
    sincos(ang, &sv, &cv);
    ct[idx] = (float)cv;
    st[idx] = (float)sv;
}

// ============================================================
// Split fp32 array into bf16 hi/lo
// ============================================================
__global__ void split_kernel(const float* __restrict__ src,
                             bf16* __restrict__ hi, bf16* __restrict__ lo,
                             int n) {
    int i = blockIdx.x * blockDim.x + threadIdx.x;
    if (i >= n) return;
    bf16 h, l;
    split_bf16(src[i], h, l);
    hi[i] = h;
    lo[i] = l;
}

// Split all three weight matrices in one launch
__global__ void split_w3_kernel(const float* __restrict__ Wq,
                                const float* __restrict__ Wk,
                                const float* __restrict__ Wv,
                                bf16* __restrict__ hi, bf16* __restrict__ lo) {
    const int nw = DIM * DIM;
    int i = blockIdx.x * blockDim.x + threadIdx.x;
    if (i >= 3 * nw) return;
    const float* src = (i < nw) ? Wq : (i < 2 * nw) ? Wk : Wv;
    float v = src[i >= 2 * nw ? i - 2 * nw : (i >= nw ? i - nw : i)];
    bf16 h, l;
    split_bf16(v, h, l);
    hi[i] = h;
    lo[i] = l;
}

// Zero the per-row sums
__global__ void zero_rsum_kernel(float* __restrict__ r) {
    int i = blockIdx.x * blockDim.x + threadIdx.x;
    if (i < MTOT) r[i] = 0.0f;
}

// ============================================================
// 3xBF16 GEMM core: acc[m,n] += sum_k A[m,k]*B[n,k] (A,B pre-split)
// Tile BM x BN x K, double-buffered cp.async pipeline, ldmatrix frags.
// ============================================================
__device__ __forceinline__ void gemm3_core(
    const bf16* __restrict__ Ahi, const bf16* __restrict__ Alo, int lda,
    const bf16* __restrict__ Bhi, const bf16* __restrict__ Blo, int ldb,
    int m0, int n0, int kSteps, float acc[4][4][4]) {
    extern __shared__ bf16 smem[];
    const int tid = threadIdx.x;
    const int wid = tid >> 5;
    const int lane = tid & 31;
    const int wm = (wid & 1) * 64;
    const int wn = (wid >> 1) * 32;

    // ldmatrix per-lane addressing
    const uint32_t a_row  = lane & 15;
    const uint32_t a_koff = (uint32_t)((lane >> 4) << 3);          // 0 or 8 elems
    const uint32_t b_row  = (uint32_t)((lane & 7) + ((lane >> 4) << 3));
    const uint32_t b_koff = (uint32_t)(((lane >> 3) & 1) << 3);    // 0 or 8 elems

    uint32_t smem_u32 = (uint32_t)__cvta_generic_to_shared(smem);

#pragma unroll
    for (int mt = 0; mt < 4; mt++)
#pragma unroll
        for (int nt = 0; nt < 4; nt++)
#pragma unroll
            for (int c = 0; c < 4; c++) acc[mt][nt][c] = 0.0f;

    const bf16* srcs[4];
    srcs[0] = Ahi + (size_t)m0 * lda;
    srcs[1] = Alo + (size_t)m0 * lda;
    srcs[2] = Bhi + (size_t)n0 * ldb;
    srcs[3] = Blo + (size_t)n0 * ldb;
    int ldsz[4] = {lda, lda, ldb, ldb};

    auto load_chunk = [&](int stage, int k0) {
#pragma unroll
        for (int i = 0; i < 8; i++) {
            const int op = i >> 1;
            const int q = tid + NTHREADS * (i & 1);  // 0..511 per operand
            const int r = q >> 2;                    // row 0..127
            const int c = (q & 3) * 8;               // bf16 col 0,8,16,24
            uint32_t dst = smem_u32 +
                (uint32_t)(((stage * 4 + op) * BUFB + r * SKB + c) * 2);
            const bf16* src = srcs[op] + (size_t)r * ldsz[op] + k0 + c;
            CP_ASYNC16(dst, src);
        }
        CP_COMMIT();
    };

    // prologue
    load_chunk(0, 0);
    CP_WAIT0();
    __syncthreads();

    for (int it = 0; it < kSteps; it++) {
        int s = it & 1;
        if (it + 1 < kSteps) load_chunk((it + 1) & 1, (it + 1) * BK);

        const uint32_t stA_h = smem_u32 + (uint32_t)((s * 4 + 0) * BUFB * 2);
        const uint32_t stA_l = smem_u32 + (uint32_t)((s * 4 + 1) * BUFB * 2);
        const uint32_t stB_h = smem_u32 + (uint32_t)((s * 4 + 2) * BUFB * 2);
        const uint32_t stB_l = smem_u32 + (uint32_t)((s * 4 + 3) * BUFB * 2);

#pragma unroll
        for (int kc = 0; kc < 2; kc++) {          // two k16 chunks per BK=32
            const uint32_t kbase = (uint32_t)(kc * 16);
            uint32_t ah[4][4], al[4][4], bh[4][2], bl[4][2];
#pragma unroll
            for (int mt = 0; mt < 4; mt++) {
                uint32_t ra = (uint32_t)(((wm + mt * 16 + a_row) * SKB + kbase + a_koff) * 2);
                LDSM_X4(ah[mt], stA_h + ra);
                LDSM_X4(al[mt], stA_l + ra);
            }
#pragma unroll
            for (int p = 0; p < 2; p++) {         // nt pairs (2p, 2p+1)
                uint32_t rb = (uint32_t)(((wn + p * 16 + b_row) * SKB + kbase + b_koff) * 2);
                uint32_t t[4];
                LDSM_X4(t, stB_h + rb);
                bh[2 * p][0] = t[0]; bh[2 * p][1] = t[1];
                bh[2 * p + 1][0] = t[2]; bh[2 * p + 1][1] = t[3];
                LDSM_X4(t, stB_l + rb);
                bl[2 * p][0] = t[0]; bl[2 * p][1] = t[1];
                bl[2 * p + 1][0] = t[2]; bl[2 * p + 1][1] = t[3];
            }
#pragma unroll
            for (int mt = 0; mt < 4; mt++)
#pragma unroll
                for (int nt = 0; nt < 4; nt++) {
                    MMA_BF16(acc[mt][nt], ah[mt], bh[nt]);
                    MMA_BF16(acc[mt][nt], ah[mt], bl[nt]);
                    MMA_BF16(acc[mt][nt], al[mt], bh[nt]);
                }
        }
        if (it + 1 < kSteps) CP_WAIT0();
        __syncthreads();
    }
}

// ============================================================
// Combined QKV projection. grid = (DIM/BN, MTOT/BM, 3)
// z=0: Q (rope+split), z=1: K (rope+split), z=2: V (transpose+split)
// ============================================================
__global__ __launch_bounds__(NTHREADS, 2)
void qkv_mma_kernel(const bf16* __restrict__ Ahi, const bf16* __restrict__ Alo,
                    const bf16* __restrict__ Whi, const bf16* __restrict__ Wlo,
                    bf16* __restrict__ Qh, bf16* __restrict__ Ql,
                    bf16* __restrict__ Kh, bf16* __restrict__ Kl,
                    bf16* __restrict__ Vth, bf16* __restrict__ Vtl,
                    const float* __restrict__ Ct, const float* __restrict__ St) {
    const int n0 = blockIdx.x * BN;
    const int m0 = blockIdx.y * BM;
    const int z  = blockIdx.z;
    const size_t nw = (size_t)DIM * DIM;

    float acc[4][4][4];
    gemm3_core(Ahi, Alo, DIM, Whi + z * nw, Wlo + z * nw, DIM, m0, n0, DIM / BK, acc);

    bf16* Ohi = (z == 0) ? Qh : (z == 1) ? Kh : Vth;
    bf16* Olo = (z == 0) ? Ql : (z == 1) ? Kl : Vtl;
    const int mode = (z == 2) ? 1 : 0;

    const int tid = threadIdx.x;
    const int wid = tid >> 5;
    const int lane = tid & 31;
    const int grp = lane >> 2;
    const int tig = lane & 3;
    const int wm = (wid & 1) * 64;
    const int wn = (wid >> 1) * 32;

#pragma unroll
    for (int mt = 0; mt < 4; mt++)
#pragma unroll
        for (int nt = 0; nt < 4; nt++)
#pragma unroll
            for (int h = 0; h < 2; h++) {
                int row = m0 + wm + mt * 16 + grp + 8 * h;
                int colE = n0 + wn + nt * 8 + tig * 2;
                float e = acc[mt][nt][2 * h];
                float o = acc[mt][nt][2 * h + 1];
                if (mode == 0) {
                    int s = row & (SEQ - 1);
                    int j = colE >> 1;
                    float cth = Ct[(size_t)s * HALF_D + j];
                    float sth = St[(size_t)s * HALF_D + j];
                    float re = e * cth - o * sth;
                    float ro = e * sth + o * cth;
                    bf16 h1, l1, h2, l2;
                    split_bf16(re, h1, l1);
                    split_bf16(ro, h2, l2);
                    size_t p = (size_t)row * DIM + colE;
                    *(bf162*)(Ohi + p) = bf162{h1, h2};
                    *(bf162*)(Olo + p) = bf162{l1, l2};
                } else {
                    int b = row >> 12;
                    int s = row & (SEQ - 1);
                    bf16 h1, l1, h2, l2;
                    split_bf16(e, h1, l1);
                    split_bf16(o, h2, l2);
                    size_t p0 = ((size_t)b * DIM + colE) * SEQ + s;
                    size_t p1 = ((size_t)b * DIM + colE + 1) * SEQ + s;
                    Ohi[p0] = h1; Olo[p0] = l1;
                    Ohi[p1] = h2; Olo[p1] = l2;
                }
            }
}

// ============================================================
// Scores+exp: E = exp((Q K^T)/32) masked causal, split bf16 output.
// (No row-max: scores are O(few), exp cannot overflow fp32; softmax
//  is shift-invariant so normalization by the row-sum suffices.)
// grid = (SEQ/BN, SEQ/BM, BATCH)
// ============================================================
__global__ __launch_bounds__(NTHREADS, 2)
void scores_mma_kernel(const bf16* __restrict__ Qhi, const bf16* __restrict__ Qlo,
                       const bf16* __restrict__ Khi, const bf16* __restrict__ Klo,
                       bf16* __restrict__ Pbh, bf16* __restrict__ Pbl) {
    const int n0 = blockIdx.x * BN;
    const int m0 = blockIdx.y * BM;
    if (n0 > m0) return;
    const int b = blockIdx.z;
    const size_t boff = (size_t)b * SEQ * DIM;

    float acc[4][4][4];
    gemm3_core(Qhi + boff, Qlo + boff, DIM, Khi + boff, Klo + boff, DIM,
               m0, n0, DIM / BK, acc);

    const int tid = threadIdx.x;
    const int wid = tid >> 5;
    const int lane = tid & 31;
    const int grp = lane >> 2;
    const int tig = lane & 3;
    const int wm = (wid & 1) * 64;
    const int wn = (wid >> 1) * 32;
    const float scale = 1.0f / 32.0f;

    bf16* Ph = Pbh + (size_t)b * SEQ * SEQ;
    bf16* Pl = Pbl + (size_t)b * SEQ * SEQ;
#pragma unroll
    for (int mt = 0; mt < 4; mt++)
#pragma unroll
        for (int nt = 0; nt < 4; nt++)
#pragma unroll
            for (int h = 0; h < 2; h++) {
                int row = m0 + wm + mt * 16 + grp + 8 * h;
                int col = n0 + wn + nt * 8 + tig * 2;
                float e0 = (col     <= row) ? expf(acc[mt][nt][2 * h]     * scale) : 0.0f;
                float e1 = (col + 1 <= row) ? expf(acc[mt][nt][2 * h + 1] * scale) : 0.0f;
                bf16 h0, l0, h1, l1;
                split_bf16(e0, h0, l0);
                split_bf16(e1, h1, l1);
                size_t p = (size_t)row * SEQ + col;
                *(bf162*)(Ph + p) = bf162{h0, h1};
                *(bf162*)(Pl + p) = bf162{l0, l1};
            }
}

// ============================================================
// Deterministic per-row sum of split exp values. Block per row.
// ============================================================
__global__ __launch_bounds__(NTHREADS)
void rowsum_kernel(const bf16* __restrict__ Pbh, const bf16* __restrict__ Pbl,
                   float* __restrict__ rsum) {
    __shared__ float red[NTHREADS / 32];
    const int rowg = blockIdx.x;
    const int b = rowg >> 12;
    const int i = rowg & (SEQ - 1);
    const bf16* ph = Pbh + ((size_t)b * SEQ + i) * SEQ;
    const bf16* pl = Pbl + ((size_t)b * SEQ + i) * SEQ;
    const int bound = (i & ~127) + 128;   // masked zeros cover (i, bound)
    const int tid = threadIdx.x;
    const int lane = tid & 31;
    const int wrp = tid >> 5;

    float sum = 0.0f;
    for (int j = tid * 2; j < bound; j += NTHREADS * 2) {
        bf162 h2 = *(const bf162*)(ph + j);
        bf162 l2 = *(const bf162*)(pl + j);
        sum += __bfloat162float(h2.x) + __bfloat162float(l2.x);
        sum += __bfloat162float(h2.y) + __bfloat162float(l2.y);
    }
#pragma unroll
    for (int o = 16; o > 0; o >>= 1) sum += __shfl_xor_sync(~0u, sum, o);
    if (lane == 0) red[wrp] = sum;
    __syncthreads();
    if (tid == 0) {
        float s = 0.0f;
#pragma unroll
        for (int w = 0; w < NTHREADS / 32; w++) s += red[w];
        rsum[rowg] = s;
    }
}

// ============================================================
// PV: O = (E @ V) / rowsum using Vt (K-major), causal-truncated k-loop.
// grid = (DIM/BN, SEQ/BM, BATCH)
// ============================================================
__global__ __launch_bounds__(NTHREADS, 2)
void pv_mma_kernel(const bf16* __restrict__ Pbh, const bf16* __restrict__ Pbl,
                   const bf16* __restrict__ Vthi, const bf16* __restrict__ Vtlo,
                   const float* __restrict__ rsum, float* __restrict__ O) {
    const int n0 = blockIdx.x * BN;
    const int m0 = blockIdx.y * BM;
    const int b = blockIdx.z;

    const bf16* Ah = Pbh + (size_t)b * SEQ * SEQ;
    const bf16* Al = Pbl + (size_t)b * SEQ * SEQ;
    const bf16* Bh = Vthi + (size_t)b * DIM * SEQ;
    const bf16* Bl = Vtlo + (size_t)b * DIM * SEQ;

    float acc[4][4][4];
    gemm3_core(Ah, Al, SEQ, Bh, Bl, SEQ, m0, n0, (m0 + BM) / BK, acc);

    const int tid = threadIdx.x;
    const int wid = tid >> 5;
    const int lane = tid & 31;
    const int grp = lane >> 2;
    const int tig = lane & 3;
    const int wm = (wid & 1) * 64;
    const int wn = (wid >> 1) * 32;

#pragma unroll
    for (int mt = 0; mt < 4; mt++)
#pragma unroll
        for (int nt = 0; nt < 4; nt++)
#pragma unroll
            for (int h = 0; h < 2; h++) {
                int row = m0 + wm + mt * 16 + grp + 8 * h;
                int col = n0 + wn + nt * 8 + tig * 2;
                float inv = 1.0f / rsum[(size_t)b * SEQ + row];
                float2 v;
                v.x = acc[mt][nt][2 * h] * inv;
                v.y = acc[mt][nt][2 * h + 1] * inv;
                *(float2*)(O + ((size_t)b * SEQ + row) * DIM + col) = v;
            }
}

// ============================================================
// Launch
// ============================================================
extern "C" void kernel_launch(void* const* d_in, const int* in_sizes, int n_in,
                              void* d_out, int out_size) {
    const float* x  = (const float*)d_in[0];
    const float* Wq = (const float*)d_in[1];
    const float* Wk = (const float*)d_in[2];
    const float* Wv = (const float*)d_in[3];
    float* out = (float*)d_out;

    bf16 *xh, *xl, *Wh, *Wl, *Qh, *Ql, *Kh, *Kl, *Vth, *Vtl, *Pbh, *Pbl;
    float *Rs, *Cp, *Sp;
    cudaGetSymbolAddress((void**)&xh, g_xhi);
    cudaGetSymbolAddress((void**)&xl, g_xlo);
    cudaGetSymbolAddress((void**)&Wh, g_Whi);
    cudaGetSymbolAddress((void**)&Wl, g_Wlo);
    cudaGetSymbolAddress((void**)&Qh, g_Qhi);
    cudaGetSymbolAddress((void**)&Ql, g_Qlo);
    cudaGetSymbolAddress((void**)&Kh, g_Khi);
    cudaGetSymbolAddress((void**)&Kl, g_Klo);
    cudaGetSymbolAddress((void**)&Vth, g_Vthi);
    cudaGetSymbolAddress((void**)&Vtl, g_Vtlo);
    cudaGetSymbolAddress((void**)&Pbh, g_Pbh);
    cudaGetSymbolAddress((void**)&Pbl, g_Pbl);
    cudaGetSymbolAddress((void**)&Rs, g_rsum);
    cudaGetSymbolAddress((void**)&Cp, g_cos);
    cudaGetSymbolAddress((void**)&Sp, g_sin);

    cudaFuncSetAttribute(qkv_mma_kernel,    cudaFuncAttributeMaxDynamicSharedMemorySize, SMEM_BYTES);
    cudaFuncSetAttribute(scores_mma_kernel, cudaFuncAttributeMaxDynamicSharedMemorySize, SMEM_BYTES);
    cudaFuncSetAttribute(pv_mma_kernel,     cudaFuncAttributeMaxDynamicSharedMemorySize, SMEM_BYTES);

    // 1) trig tables
    {
        int total = SEQ * HALF_D;
        trig_table_kernel<<<(total + 255) / 256, 256>>>(Cp, Sp);
    }
    // 2) split x
    {
        int nx = MTOT * DIM;
        split_kernel<<<(nx + 255) / 256, 256>>>(x, xh, xl, nx);
    }
    // 3) split all weights (one launch)
    {
        int n3 = 3 * DIM * DIM;
        split_w3_kernel<<<(n3 + 255) / 256, 256>>>(Wq, Wk, Wv, Wh, Wl);
    }
    // 4) zero row sums
    zero_rsum_kernel<<<(MTOT + 255) / 256, 256>>>(Rs);

    // 5) QKV projections (single launch, grid.z selects Q/K/V)
    {
        dim3 grid(DIM / BN, MTOT / BM, 3);   // (8, 128, 3)
        qkv_mma_kernel<<<grid, NTHREADS, SMEM_BYTES>>>(xh, xl, Wh, Wl,
                                                       Qh, Ql, Kh, Kl, Vth, Vtl,
                                                       Cp, Sp);
    }
    // 6) scores + exp + causal mask (split output, no softmax pass)
    {
        dim3 grid(SEQ / BN, SEQ / BM, BATCH);
        scores_mma_kernel<<<grid, NTHREADS, SMEM_BYTES>>>(Qh, Ql, Kh, Kl, Pbh, Pbl);
    }
    // 7) deterministic row sums
    rowsum_kernel<<<BATCH * SEQ, NTHREADS>>>(Pbh, Pbl, Rs);

    // 8) O = (E @ V) / rowsum
    {
        dim3 grid(DIM / BN, SEQ / BM, BATCH);
        pv_mma_kernel<<<grid, NTHREADS, SMEM_BYTES>>>(Pbh, Pbl, Vth, Vtl, Rs, out);
    }
}

// round 11
// speedup vs baseline: 2.8127x; 1.0351x over previous
#include <cuda_runtime.h>
#include <cuda_bf16.h>
#include <math.h>
#include <stdint.h>

typedef __nv_bfloat16 bf16;
typedef __nv_bfloat162 bf162;

// Problem constants
#define BATCH 4
#define SEQ   4096
#define DIM   1024
#define MTOT  (BATCH * SEQ)     // 16384
#define HALF_D (DIM / 2)        // 512

// GEMM tiling
#define BM 128
#define BN 128
#define BK 32
#define NTHREADS 256
#define SKB 40                          // padded smem row stride (bf16 elems) = 80 bytes
#define BUFB (BM * SKB)                 // 5120 bf16 per operand buffer
#define SMEM_BYTES (2 * 4 * BUFB * 2)   // 2 stages x 4 operands x bf16 = 81920 B
#define VSTRIDE 132                     // fp32 stage buffer column stride

// -------- device scratch (no cudaMalloc allowed) --------
__device__ bf16 g_xhi[(size_t)MTOT * DIM];
__device__ bf16 g_xlo[(size_t)MTOT * DIM];
__device__ bf16 g_Whi[(size_t)3 * DIM * DIM];
__device__ bf16 g_Wlo[(size_t)3 * DIM * DIM];
__device__ bf16 g_Qhi[(size_t)MTOT * DIM];
__device__ bf16 g_Qlo[(size_t)MTOT * DIM];
__device__ bf16 g_Khi[(size_t)MTOT * DIM];
__device__ bf16 g_Klo[(size_t)MTOT * DIM];
__device__ bf16 g_Vthi[(size_t)MTOT * DIM];   // [b][dim][seq]
__device__ bf16 g_Vtlo[(size_t)MTOT * DIM];
__device__ bf16 g_Pbh[(size_t)BATCH * SEQ * SEQ];   // unnormalized exp(scores), split
__device__ bf16 g_Pbl[(size_t)BATCH * SEQ * SEQ];
__device__ float g_rsum[(size_t)MTOT];              // per-row sum of exp
__device__ float g_cos[(size_t)SEQ * HALF_D];
__device__ float g_sin[(size_t)SEQ * HALF_D];

// ============================================================
// helpers
// ============================================================
__device__ __forceinline__ void split_bf16(float x, bf16& hi, bf16& lo) {
    hi = __float2bfloat16_rn(x);
    lo = __float2bfloat16_rn(x - __bfloat162float(hi));
}

#define MMA_BF16(D, A, B)                                                   \
    asm volatile(                                                           \
        "mma.sync.aligned.m16n8k16.row.col.f32.bf16.bf16.f32 "              \
        "{%0,%1,%2,%3}, {%4,%5,%6,%7}, {%8,%9}, {%0,%1,%2,%3};"             \
        : "+f"((D)[0]), "+f"((D)[1]), "+f"((D)[2]), "+f"((D)[3])            \
        : "r"((A)[0]), "r"((A)[1]), "r"((A)[2]), "r"((A)[3]),               \
          "r"((B)[0]), "r"((B)[1]))

#define LDSM_X4(R, addr)                                                    \
    asm volatile(                                                           \
        "ldmatrix.sync.aligned.m8n8.x4.shared.b16 {%0,%1,%2,%3}, [%4];"     \
        : "=r"((R)[0]), "=r"((R)[1]), "=r"((R)[2]), "=r"((R)[3])            \
        : "r"(addr))

#define CP_ASYNC16(dst, src)                                                \
    asm volatile("cp.async.cg.shared.global [%0], [%1], 16;"                \
                 :: "r"(dst), "l"(src))
#define CP_COMMIT() asm volatile("cp.async.commit_group;")
#define CP_WAIT0()  asm volatile("cp.async.wait_group 0;")

// ============================================================
// RoPE cos/sin table (double precision generation)
// ============================================================
__global__ void trig_table_kernel(float* ct, float* st) {
    int idx = blockIdx.x * blockDim.x + threadIdx.x;
    if (idx >= SEQ * HALF_D) return;
    int s = idx / HALF_D;
    int j = idx % HALF_D;
    double inv = exp(-((double)(2 * j) / (double)DIM) * 9.210340371976184);
    double ang = (double)s * inv;
    double sv, cv;
    sincos(ang, &sv, &cv);
    ct[idx] = (float)cv;
    st[idx] = (float)sv;
}

// ============================================================
// Split fp32 array into bf16 hi/lo
// ============================================================
__global__ void split_kernel(const float* __restrict__ src,
                             bf16* __restrict__ hi, bf16* __restrict__ lo,
                             int n) {
    int i = blockIdx.x * blockDim.x + threadIdx.x;
    if (i >= n) return;
    bf16 h, l;
    split_bf16(src[i], h, l);
    hi[i] = h;
    lo[i] = l;
}

// Split all three weight matrices in one launch
__global__ void split_w3_kernel(const float* __restrict__ Wq,
                                const float* __restrict__ Wk,
                                const float* __restrict__ Wv,
                                bf16* __restrict__ hi, bf16* __restrict__ lo) {
    const int nw = DIM * DIM;
    int i = blockIdx.x * blockDim.x + threadIdx.x;
    if (i >= 3 * nw) return;
    const float* src = (i < nw) ? Wq : (i < 2 * nw) ? Wk : Wv;
    float v = src[i >= 2 * nw ? i - 2 * nw : (i >= nw ? i - nw : i)];
    bf16 h, l;
    split_bf16(v, h, l);
    hi[i] = h;
    lo[i] = l;
}

// ============================================================
// 3xBF16 GEMM core: acc[m,n] += sum_k A[m,k]*B[n,k] (A,B pre-split)
// Tile BM x BN x K, double-buffered cp.async pipeline, ldmatrix frags.
// ============================================================
__device__ __forceinline__ void gemm3_core(
    const bf16* __restrict__ Ahi, const bf16* __restrict__ Alo, int lda,
    const bf16* __restrict__ Bhi, const bf16* __restrict__ Blo, int ldb,
    int m0, int n0, int kSteps, float acc[4][4][4]) {
    extern __shared__ bf16 smem[];
    const int tid = threadIdx.x;
    const int wid = tid >> 5;
    const int lane = tid & 31;
    const int wm = (wid & 1) * 64;
    const int wn = (wid >> 1) * 32;

    // ldmatrix per-lane addressing
    const uint32_t a_row  = lane & 15;
    const uint32_t a_koff = (uint32_t)((lane >> 4) << 3);          // 0 or 8 elems
    const uint32_t b_row  = (uint32_t)((lane & 7) + ((lane >> 4) << 3));
    const uint32_t b_koff = (uint32_t)(((lane >> 3) & 1) << 3);    // 0 or 8 elems

    uint32_t smem_u32 = (uint32_t)__cvta_generic_to_shared(smem);

#pragma unroll
    for (int mt = 0; mt < 4; mt++)
#pragma unroll
        for (int nt = 0; nt < 4; nt++)
#pragma unroll
            for (int c = 0; c < 4; c++) acc[mt][nt][c] = 0.0f;

    const bf16* srcs[4];
    srcs[0] = Ahi + (size_t)m0 * lda;
    srcs[1] = Alo + (size_t)m0 * lda;
    srcs[2] = Bhi + (size_t)n0 * ldb;
    srcs[3] = Blo + (size_t)n0 * ldb;
    int ldsz[4] = {lda, lda, ldb, ldb};

    auto load_chunk = [&](int stage, int k0) {
#pragma unroll
        for (int i = 0; i < 8; i++) {
            const int op = i >> 1;
            const int q = tid + NTHREADS * (i & 1);  // 0..511 per operand
            const int r = q >> 2;                    // row 0..127
            const int c = (q & 3) * 8;               // bf16 col 0,8,16,24
            uint32_t dst = smem_u32 +
                (uint32_t)(((stage * 4 + op) * BUFB + r * SKB + c) * 2);
            const bf16* src = srcs[op] + (size_t)r * ldsz[op] + k0 + c;
            CP_ASYNC16(dst, src);
        }
        CP_COMMIT();
    };

    // prologue
    load_chunk(0, 0);
    CP_WAIT0();
    __syncthreads();

    for (int it = 0; it < kSteps; it++) {
        int s = it & 1;
        if (it + 1 < kSteps) load_chunk((it + 1) & 1, (it + 1) * BK);

        const uint32_t stA_h = smem_u32 + (uint32_t)((s * 4 + 0) * BUFB * 2);
        const uint32_t stA_l = smem_u32 + (uint32_t)((s * 4 + 1) * BUFB * 2);
        const uint32_t stB_h = smem_u32 + (uint32_t)((s * 4 + 2) * BUFB * 2);
        const uint32_t stB_l = smem_u32 + (uint32_t)((s * 4 + 3) * BUFB * 2);

#pragma unroll
        for (int kc = 0; kc < 2; kc++) {          // two k16 chunks per BK=32
            const uint32_t kbase = (uint32_t)(kc * 16);
            uint32_t ah[4][4], al[4][4], bh[4][2], bl[4][2];
#pragma unroll
            for (int mt = 0; mt < 4; mt++) {
                uint32_t ra = (uint32_t)(((wm + mt * 16 + a_row) * SKB + kbase + a_koff) * 2);
                LDSM_X4(ah[mt], stA_h + ra);
                LDSM_X4(al[mt], stA_l + ra);
            }
#pragma unroll
            for (int p = 0; p < 2; p++) {         // nt pairs (2p, 2p+1)
                uint32_t rb = (uint32_t)(((wn + p * 16 + b_row) * SKB + kbase + b_koff) * 2);
                uint32_t t[4];
                LDSM_X4(t, stB_h + rb);
                bh[2 * p][0] = t[0]; bh[2 * p][1] = t[1];
                bh[2 * p + 1][0] = t[2]; bh[2 * p + 1][1] = t[3];
                LDSM_X4(t, stB_l + rb);
                bl[2 * p][0] = t[0]; bl[2 * p][1] = t[1];
                bl[2 * p + 1][0] = t[2]; bl[2 * p + 1][1] = t[3];
            }
#pragma unroll
            for (int mt = 0; mt < 4; mt++)
#pragma unroll
                for (int nt = 0; nt < 4; nt++) {
                    MMA_BF16(acc[mt][nt], ah[mt], bh[nt]);
                    MMA_BF16(acc[mt][nt], ah[mt], bl[nt]);
                    MMA_BF16(acc[mt][nt], al[mt], bh[nt]);
                }
        }
        if (it + 1 < kSteps) CP_WAIT0();
        __syncthreads();
    }
}

// ============================================================
// Combined QKV projection. grid = (DIM/BN, MTOT/BM, 3)
// z=0: Q (rope+split), z=1: K (rope+split), z=2: V (smem-staged
// transposed coalesced split store)
// ============================================================
__global__ __launch_bounds__(NTHREADS, 2)
void qkv_mma_kernel(const bf16* __restrict__ Ahi, const bf16* __restrict__ Alo,
                    const bf16* __restrict__ Whi, const bf16* __restrict__ Wlo,
                    bf16* __restrict__ Qh, bf16* __restrict__ Ql,
                    bf16* __restrict__ Kh, bf16* __restrict__ Kl,
                    bf16* __restrict__ Vth, bf16* __restrict__ Vtl,
                    const float* __restrict__ Ct, const float* __restrict__ St) {
    const int n0 = blockIdx.x * BN;
    const int m0 = blockIdx.y * BM;
    const int z  = blockIdx.z;
    const size_t nw = (size_t)DIM * DIM;

    float acc[4][4][4];
    gemm3_core(Ahi, Alo, DIM, Whi + z * nw, Wlo + z * nw, DIM, m0, n0, DIM / BK, acc);

    const int tid = threadIdx.x;
    const int wid = tid >> 5;
    const int lane = tid & 31;
    const int grp = lane >> 2;
    const int tig = lane & 3;
    const int wm = (wid & 1) * 64;
    const int wn = (wid >> 1) * 32;

    if (z != 2) {
        bf16* Ohi = (z == 0) ? Qh : Kh;
        bf16* Olo = (z == 0) ? Ql : Kl;
#pragma unroll
        for (int mt = 0; mt < 4; mt++)
#pragma unroll
            for (int nt = 0; nt < 4; nt++)
#pragma unroll
                for (int h = 0; h < 2; h++) {
                    int row = m0 + wm + mt * 16 + grp + 8 * h;
                    int colE = n0 + wn + nt * 8 + tig * 2;
                    float e = acc[mt][nt][2 * h];
                    float o = acc[mt][nt][2 * h + 1];
                    int s = row & (SEQ - 1);
                    int j = colE >> 1;
                    float cth = Ct[(size_t)s * HALF_D + j];
                    float sth = St[(size_t)s * HALF_D + j];
                    float re = e * cth - o * sth;
                    float ro = e * sth + o * cth;
                    bf16 h1, l1, h2, l2;
                    split_bf16(re, h1, l1);
                    split_bf16(ro, h2, l2);
                    size_t p = (size_t)row * DIM + colE;
                    *(bf162*)(Ohi + p) = bf162{h1, h2};
                    *(bf162*)(Olo + p) = bf162{l1, l2};
                }
    } else {
        // ---- V: stage fp32 tile in smem as [col][row], then coalesced
        //      transposed split stores (16B chunks along seq). ----
        extern __shared__ bf16 smem[];
        float* vbuf = (float*)smem;   // 128 cols x VSTRIDE floats = 67.6 KB <= 80 KB
        // mainloop ended with __syncthreads(); smem free to reuse
#pragma unroll
        for (int mt = 0; mt < 4; mt++)
#pragma unroll
            for (int nt = 0; nt < 4; nt++)
#pragma unroll
                for (int h = 0; h < 2; h++) {
                    int rowL = wm + mt * 16 + grp + 8 * h;
                    int colL = wn + nt * 8 + tig * 2;
                    vbuf[colL * VSTRIDE + rowL]       = acc[mt][nt][2 * h];
                    vbuf[(colL + 1) * VSTRIDE + rowL] = acc[mt][nt][2 * h + 1];
                }
        __syncthreads();

        const int bq = m0 >> 12;          // batch (tiles never straddle)
        const int sbase = m0 & (SEQ - 1);
        const int col = tid >> 1;          // 0..127
        const int half = tid & 1;          // seq half: 0 or 64
        const float* srcc = vbuf + col * VSTRIDE + half * 64;
        size_t gbase = ((size_t)bq * DIM + n0 + col) * SEQ + sbase + half * 64;
#pragma unroll
        for (int j0 = 0; j0 < 64; j0 += 8) {
            bf16 h8[8], l8[8];
#pragma unroll
            for (int j = 0; j < 8; j++) split_bf16(srcc[j0 + j], h8[j], l8[j]);
            *(uint4*)(Vth + gbase + j0) = *(uint4*)h8;
            *(uint4*)(Vtl + gbase + j0) = *(uint4*)l8;
        }
    }
}

// ============================================================
// Scores+exp: E = exp((Q K^T)/32) masked causal, split bf16 output.
// (No row-max: scores are O(few), exp cannot overflow fp32; softmax
//  is shift-invariant so normalization by the row-sum suffices.)
// grid = (SEQ/BN, SEQ/BM, BATCH)
// ============================================================
__global__ __launch_bounds__(NTHREADS, 2)
void scores_mma_kernel(const bf16* __restrict__ Qhi, const bf16* __restrict__ Qlo,
                       const bf16* __restrict__ Khi, const bf16* __restrict__ Klo,
                       bf16* __restrict__ Pbh, bf16* __restrict__ Pbl) {
    const int n0 = blockIdx.x * BN;
    const int m0 = blockIdx.y * BM;
    if (n0 > m0) return;
    const int b = blockIdx.z;
    const size_t boff = (size_t)b * SEQ * DIM;

    float acc[4][4][4];
    gemm3_core(Qhi + boff, Qlo + boff, DIM, Khi + boff, Klo + boff, DIM,
               m0, n0, DIM / BK, acc);

    const int tid = threadIdx.x;
    const int wid = tid >> 5;
    const int lane = tid & 31;
    const int grp = lane >> 2;
    const int tig = lane & 3;
    const int wm = (wid & 1) * 64;
    const int wn = (wid >> 1) * 32;
    const float scale = 1.0f / 32.0f;

    bf16* Ph = Pbh + (size_t)b * SEQ * SEQ;
    bf16* Pl = Pbl + (size_t)b * SEQ * SEQ;
#pragma unroll
    for (int mt = 0; mt < 4; mt++)
#pragma unroll
        for (int nt = 0; nt < 4; nt++)
#pragma unroll
            for (int h = 0; h < 2; h++) {
                int row = m0 + wm + mt * 16 + grp + 8 * h;
                int col = n0 + wn + nt * 8 + tig * 2;
                float e0 = (col     <= row) ? __expf(acc[mt][nt][2 * h]     * scale) : 0.0f;
                float e1 = (col + 1 <= row) ? __expf(acc[mt][nt][2 * h + 1] * scale) : 0.0f;
                bf16 h0, l0, h1, l1;
                split_bf16(e0, h0, l0);
                split_bf16(e1, h1, l1);
                size_t p = (size_t)row * SEQ + col;
                *(bf162*)(Ph + p) = bf162{h0, h1};
                *(bf162*)(Pl + p) = bf162{l0, l1};
            }
}

// ============================================================
// Deterministic per-row sum of split exp values. Block per row.
// ============================================================
__global__ __launch_bounds__(NTHREADS)
void rowsum_kernel(const bf16* __restrict__ Pbh, const bf16* __restrict__ Pbl,
                   float* __restrict__ rsum) {
    __shared__ float red[NTHREADS / 32];
    const int rowg = blockIdx.x;
    const int b = rowg >> 12;
    const int i = rowg & (SEQ - 1);
    const bf16* ph = Pbh + ((size_t)b * SEQ + i) * SEQ;
    const bf16* pl = Pbl + ((size_t)b * SEQ + i) * SEQ;
    const int bound = (i & ~127) + 128;   // masked zeros cover (i, bound)
    const int tid = threadIdx.x;
    const int lane = tid & 31;
    const int wrp = tid >> 5;

    float sum = 0.0f;
    for (int j = tid * 2; j < bound; j += NTHREADS * 2) {
        bf162 h2 = *(const bf162*)(ph + j);
        bf162 l2 = *(const bf162*)(pl + j);
        sum += __bfloat162float(h2.x) + __bfloat162float(l2.x);
        sum += __bfloat162float(h2.y) + __bfloat162float(l2.y);
    }
#pragma unroll
    for (int o = 16; o > 0; o >>= 1) sum += __shfl_xor_sync(~0u, sum, o);
    if (lane == 0) red[wrp] = sum;
    __syncthreads();
    if (tid == 0) {
        float s = 0.0f;
#pragma unroll
        for (int w = 0; w < NTHREADS / 32; w++) s += red[w];
        rsum[rowg] = s;
    }
}

// ============================================================
// PV: O = (E @ V) / rowsum using Vt (K-major), causal-truncated k-loop.
// grid = (DIM/BN, SEQ/BM, BATCH); m-tiles reversed so heavy tiles go first.
// ============================================================
__global__ __launch_bounds__(NTHREADS, 2)
void pv_mma_kernel(const bf16* __restrict__ Pbh, const bf16* __restrict__ Pbl,
                   const bf16* __restrict__ Vthi, const bf16* __restrict__ Vtlo,
                   const float* __restrict__ rsum, float* __restrict__ O) {
    const int n0 = blockIdx.x * BN;
    const int m0 = (int)(gridDim.y - 1 - blockIdx.y) * BM;   // heavy first
    const int b = blockIdx.z;

    const bf16* Ah = Pbh + (size_t)b * SEQ * SEQ;
    const bf16* Al = Pbl + (size_t)b * SEQ * SEQ;
    const bf16* Bh = Vthi + (size_t)b * DIM * SEQ;
    const bf16* Bl = Vtlo + (size_t)b * DIM * SEQ;

    float acc[4][4][4];
    gemm3_core(Ah, Al, SEQ, Bh, Bl, SEQ, m0, n0, (m0 + BM) / BK, acc);

    const int tid = threadIdx.x;
    const int wid = tid >> 5;
    const int lane = tid & 31;
    const int grp = lane >> 2;
    const int tig = lane & 3;
    const int wm = (wid & 1) * 64;
    const int wn = (wid >> 1) * 32;

#pragma unroll
    for (int mt = 0; mt < 4; mt++)
#pragma unroll
        for (int nt = 0; nt < 4; nt++)
#pragma unroll
            for (int h = 0; h < 2; h++) {
                int row = m0 + wm + mt * 16 + grp + 8 * h;
                int col = n0 + wn + nt * 8 + tig * 2;
                float inv = 1.0f / rsum[(size_t)b * SEQ + row];
                float2 v;
                v.x = acc[mt][nt][2 * h] * inv;
                v.y = acc[mt][nt][2 * h + 1] * inv;
                *(float2*)(O + ((size_t)b * SEQ + row) * DIM + col) = v;
            }
}

// ============================================================
// Launch
// ============================================================
extern "C" void kernel_launch(void* const* d_in, const int* in_sizes, int n_in,
                              void* d_out, int out_size) {
    const float* x  = (const float*)d_in[0];
    const float* Wq = (const float*)d_in[1];
    const float* Wk = (const float*)d_in[2];
    const float* Wv = (const float*)d_in[3];
    float* out = (float*)d_out;

    bf16 *xh, *xl, *Wh, *Wl, *Qh, *Ql, *Kh, *Kl, *Vth, *Vtl, *Pbh, *Pbl;
    float *Rs, *Cp, *Sp;
    cudaGetSymbolAddress((void**)&xh, g_xhi);
    cudaGetSymbolAddress((void**)&xl, g_xlo);
    cudaGetSymbolAddress((void**)&Wh, g_Whi);
    cudaGetSymbolAddress((void**)&Wl, g_Wlo);
    cudaGetSymbolAddress((void**)&Qh, g_Qhi);
    cudaGetSymbolAddress((void**)&Ql, g_Qlo);
    cudaGetSymbolAddress((void**)&Kh, g_Khi);
    cudaGetSymbolAddress((void**)&Kl, g_Klo);
    cudaGetSymbolAddress((void**)&Vth, g_Vthi);
    cudaGetSymbolAddress((void**)&Vtl, g_Vtlo);
    cudaGetSymbolAddress((void**)&Pbh, g_Pbh);
    cudaGetSymbolAddress((void**)&Pbl, g_Pbl);
    cudaGetSymbolAddress((void**)&Rs, g_rsum);
    cudaGetSymbolAddress((void**)&Cp, g_cos);
    cudaGetSymbolAddress((void**)&Sp, g_sin);

    cudaFuncSetAttribute(qkv_mma_kernel,    cudaFuncAttributeMaxDynamicSharedMemorySize, SMEM_BYTES);
    cudaFuncSetAttribute(scores_mma_kernel, cudaFuncAttributeMaxDynamicSharedMemorySize, SMEM_BYTES);
    cudaFuncSetAttribute(pv_mma_kernel,     cudaFuncAttributeMaxDynamicSharedMemorySize, SMEM_BYTES);

    // 1) trig tables
    {
        int total = SEQ * HALF_D;
        trig_table_kernel<<<(total + 255) / 256, 256>>>(Cp, Sp);
    }
    // 2) split x
    {
        int nx = MTOT * DIM;
        split_kernel<<<(nx + 255) / 256, 256>>>(x, xh, xl, nx);
    }
    // 3) split all weights (one launch)
    {
        int n3 = 3 * DIM * DIM;
        split_w3_kernel<<<(n3 + 255) / 256, 256>>>(Wq, Wk, Wv, Wh, Wl);
    }

    // 4) QKV projections (single launch, grid.z selects Q/K/V)
    {
        dim3 grid(DIM / BN, MTOT / BM, 3);   // (8, 128, 3)
        qkv_mma_kernel<<<grid, NTHREADS, SMEM_BYTES>>>(xh, xl, Wh, Wl,
                                                       Qh, Ql, Kh, Kl, Vth, Vtl,
                                                       Cp, Sp);
    }
    // 5) scores + exp + causal mask (split output, no softmax pass)
    {
        dim3 grid(SEQ / BN, SEQ / BM, BATCH);
        scores_mma_kernel<<<grid, NTHREADS, SMEM_BYTES>>>(Qh, Ql, Kh, Kl, Pbh, Pbl);
    }
    // 6) deterministic row sums
    rowsum_kernel<<<BATCH * SEQ, NTHREADS>>>(Pbh, Pbl, Rs);

    // 7) O = (E @ V) / rowsum
    {
        dim3 grid(DIM / BN, SEQ / BM, BATCH);
        pv_mma_kernel<<<grid, NTHREADS, SMEM_BYTES>>>(Pbh, Pbl, Vth, Vtl, Rs, out);
    }
}

// round 12
// speedup vs baseline: 2.9504x; 1.0490x over previous
#include <cuda_runtime.h>
#include <cuda_bf16.h>
#include <math.h>
#include <stdint.h>

typedef __nv_bfloat16 bf16;
typedef __nv_bfloat162 bf162;

// Problem constants
#define BATCH 4
#define SEQ   4096
#define DIM   1024
#define MTOT  (BATCH * SEQ)     // 16384
#define HALF_D (DIM / 2)        // 512

// GEMM tiling: 128x128 CTA tile, 4 warps of 64x64
#define BM 128
#define BN 128
#define BK 32
#define GTH 128                         // gemm block threads (4 warps)
#define NTHREADS 256                    // helper-kernel block size
#define SKB 40                          // padded smem row stride (bf16) = 80 B
#define BUFB (BM * SKB)                 // 5120 bf16 per operand buffer
#define SMEM_BYTES (2 * 4 * BUFB * 2)   // 2 stages x 4 operands x bf16 = 81920 B
#define VSTRIDE 133                     // fp32 stage buffer column stride (conflict-free)

// -------- device scratch (no cudaMalloc allowed) --------
__device__ bf16 g_xhi[(size_t)MTOT * DIM];
__device__ bf16 g_xlo[(size_t)MTOT * DIM];
__device__ bf16 g_Whi[(size_t)3 * DIM * DIM];
__device__ bf16 g_Wlo[(size_t)3 * DIM * DIM];
__device__ bf16 g_Qhi[(size_t)MTOT * DIM];
__device__ bf16 g_Qlo[(size_t)MTOT * DIM];
__device__ bf16 g_Khi[(size_t)MTOT * DIM];
__device__ bf16 g_Klo[(size_t)MTOT * DIM];
__device__ bf16 g_Vthi[(size_t)MTOT * DIM];   // [b][dim][seq]
__device__ bf16 g_Vtlo[(size_t)MTOT * DIM];
__device__ bf16 g_Pbh[(size_t)BATCH * SEQ * SEQ];   // unnormalized exp(scores), split
__device__ bf16 g_Pbl[(size_t)BATCH * SEQ * SEQ];
__device__ float g_rsum[(size_t)MTOT];              // per-row sum of exp
__device__ float g_cos[(size_t)SEQ * HALF_D];
__device__ float g_sin[(size_t)SEQ * HALF_D];

// ============================================================
// helpers
// ============================================================
__device__ __forceinline__ void split_bf16(float x, bf16& hi, bf16& lo) {
    hi = __float2bfloat16_rn(x);
    lo = __float2bfloat16_rn(x - __bfloat162float(hi));
}

#define MMA_BF16(D, A, B)                                                   \
    asm volatile(                                                           \
        "mma.sync.aligned.m16n8k16.row.col.f32.bf16.bf16.f32 "              \
        "{%0,%1,%2,%3}, {%4,%5,%6,%7}, {%8,%9}, {%0,%1,%2,%3};"             \
        : "+f"((D)[0]), "+f"((D)[1]), "+f"((D)[2]), "+f"((D)[3])            \
        : "r"((A)[0]), "r"((A)[1]), "r"((A)[2]), "r"((A)[3]),               \
          "r"((B)[0]), "r"((B)[1]))

#define LDSM_X4(R, addr)                                                    \
    asm volatile(                                                           \
        "ldmatrix.sync.aligned.m8n8.x4.shared.b16 {%0,%1,%2,%3}, [%4];"     \
        : "=r"((R)[0]), "=r"((R)[1]), "=r"((R)[2]), "=r"((R)[3])            \
        : "r"(addr))

#define CP_ASYNC16(dst, src)                                                \
    asm volatile("cp.async.cg.shared.global [%0], [%1], 16;"                \
                 :: "r"(dst), "l"(src))
#define CP_COMMIT() asm volatile("cp.async.commit_group;")
#define CP_WAIT0()  asm volatile("cp.async.wait_group 0;")

// ============================================================
// RoPE cos/sin table (double precision generation)
// ============================================================
__global__ void trig_table_kernel(float* ct, float* st) {
    int idx = blockIdx.x * blockDim.x + threadIdx.x;
    if (idx >= SEQ * HALF_D) return;
    int s = idx / HALF_D;
    int j = idx % HALF_D;
    double inv = exp(-((double)(2 * j) / (double)DIM) * 9.210340371976184);
    double ang = (double)s * inv;
    double sv, cv;
    sincos(ang, &sv, &cv);
    ct[idx] = (float)cv;
    st[idx] = (float)sv;
}

// ============================================================
// Split fp32 array into bf16 hi/lo
// ============================================================
__global__ void split_kernel(const float* __restrict__ src,
                             bf16* __restrict__ hi, bf16* __restrict__ lo,
                             int n) {
    int i = blockIdx.x * blockDim.x + threadIdx.x;
    if (i >= n) return;
    bf16 h, l;
    split_bf16(src[i], h, l);
    hi[i] = h;
    lo[i] = l;
}

// Split all three weight matrices in one launch
__global__ void split_w3_kernel(const float* __restrict__ Wq,
                                const float* __restrict__ Wk,
                                const float* __restrict__ Wv,
                                bf16* __restrict__ hi, bf16* __restrict__ lo) {
    const int nw = DIM * DIM;
    int i = blockIdx.x * blockDim.x + threadIdx.x;
    if (i >= 3 * nw) return;
    const float* src = (i < nw) ? Wq : (i < 2 * nw) ? Wk : Wv;
    float v = src[i >= 2 * nw ? i - 2 * nw : (i >= nw ? i - nw : i)];
    bf16 h, l;
    split_bf16(v, h, l);
    hi[i] = h;
    lo[i] = l;
}

// ============================================================
// 3xBF16 GEMM core, 4 warps x (64x64) warp tiles.
// acc[mt][nt][4]: mt 0..3 (m16), nt 0..7 (n8).
// ============================================================
__device__ __forceinline__ void gemm3_core(
    const bf16* __restrict__ Ahi, const bf16* __restrict__ Alo, int lda,
    const bf16* __restrict__ Bhi, const bf16* __restrict__ Blo, int ldb,
    int m0, int n0, int kSteps, float acc[4][8][4]) {
    extern __shared__ bf16 smem[];
    const int tid = threadIdx.x;
    const int wid = tid >> 5;          // 0..3
    const int lane = tid & 31;
    const int wm = (wid & 1) * 64;
    const int wn = (wid >> 1) * 64;

    // ldmatrix per-lane addressing
    const uint32_t a_row  = lane & 15;
    const uint32_t a_koff = (uint32_t)((lane >> 4) << 3);          // 0 or 8 elems
    const uint32_t b_row  = (uint32_t)((lane & 7) + ((lane >> 4) << 3));
    const uint32_t b_koff = (uint32_t)(((lane >> 3) & 1) << 3);    // 0 or 8 elems

    uint32_t smem_u32 = (uint32_t)__cvta_generic_to_shared(smem);

#pragma unroll
    for (int mt = 0; mt < 4; mt++)
#pragma unroll
        for (int nt = 0; nt < 8; nt++)
#pragma unroll
            for (int c = 0; c < 4; c++) acc[mt][nt][c] = 0.0f;

    const bf16* srcs[4];
    srcs[0] = Ahi + (size_t)m0 * lda;
    srcs[1] = Alo + (size_t)m0 * lda;
    srcs[2] = Bhi + (size_t)n0 * ldb;
    srcs[3] = Blo + (size_t)n0 * ldb;
    int ldsz[4] = {lda, lda, ldb, ldb};

    auto load_chunk = [&](int stage, int k0) {
#pragma unroll
        for (int i = 0; i < 16; i++) {
            const int op = i >> 2;
            const int q = tid + GTH * (i & 3);       // 0..511 per operand
            const int r = q >> 2;                    // row 0..127
            const int c = (q & 3) * 8;               // bf16 col 0,8,16,24
            uint32_t dst = smem_u32 +
                (uint32_t)(((stage * 4 + op) * BUFB + r * SKB + c) * 2);
            const bf16* src = srcs[op] + (size_t)r * ldsz[op] + k0 + c;
            CP_ASYNC16(dst, src);
        }
        CP_COMMIT();
    };

    // prologue
    load_chunk(0, 0);
    CP_WAIT0();
    __syncthreads();

    for (int it = 0; it < kSteps; it++) {
        int s = it & 1;
        if (it + 1 < kSteps) load_chunk((it + 1) & 1, (it + 1) * BK);

        const uint32_t stA_h = smem_u32 + (uint32_t)((s * 4 + 0) * BUFB * 2);
        const uint32_t stA_l = smem_u32 + (uint32_t)((s * 4 + 1) * BUFB * 2);
        const uint32_t stB_h = smem_u32 + (uint32_t)((s * 4 + 2) * BUFB * 2);
        const uint32_t stB_l = smem_u32 + (uint32_t)((s * 4 + 3) * BUFB * 2);

#pragma unroll
        for (int kc = 0; kc < 2; kc++) {          // two k16 chunks per BK=32
            const uint32_t kbase = (uint32_t)(kc * 16);
            uint32_t ah[4][4], al[4][4], bh[8][2], bl[8][2];
#pragma unroll
            for (int mt = 0; mt < 4; mt++) {
                uint32_t ra = (uint32_t)(((wm + mt * 16 + a_row) * SKB + kbase + a_koff) * 2);
                LDSM_X4(ah[mt], stA_h + ra);
                LDSM_X4(al[mt], stA_l + ra);
            }
#pragma unroll
            for (int p = 0; p < 4; p++) {         // nt pairs (2p, 2p+1)
                uint32_t rb = (uint32_t)(((wn + p * 16 + b_row) * SKB + kbase + b_koff) * 2);
                uint32_t t[4];
                LDSM_X4(t, stB_h + rb);
                bh[2 * p][0] = t[0]; bh[2 * p][1] = t[1];
                bh[2 * p + 1][0] = t[2]; bh[2 * p + 1][1] = t[3];
                LDSM_X4(t, stB_l + rb);
                bl[2 * p][0] = t[0]; bl[2 * p][1] = t[1];
                bl[2 * p + 1][0] = t[2]; bl[2 * p + 1][1] = t[3];
            }
#pragma unroll
            for (int mt = 0; mt < 4; mt++)
#pragma unroll
                for (int nt = 0; nt < 8; nt++) {
                    MMA_BF16(acc[mt][nt], ah[mt], bh[nt]);
                    MMA_BF16(acc[mt][nt], ah[mt], bl[nt]);
                    MMA_BF16(acc[mt][nt], al[mt], bh[nt]);
                }
        }
        if (it + 1 < kSteps) CP_WAIT0();
        __syncthreads();
    }
}

// ============================================================
// Combined QKV projection. grid = (DIM/BN, MTOT/BM, 3)
// z=0: Q (rope+split), z=1: K (rope+split), z=2: V (smem-staged
// transposed coalesced split store)
// ============================================================
__global__ __launch_bounds__(GTH, 2)
void qkv_mma_kernel(const bf16* __restrict__ Ahi, const bf16* __restrict__ Alo,
                    const bf16* __restrict__ Whi, const bf16* __restrict__ Wlo,
                    bf16* __restrict__ Qh, bf16* __restrict__ Ql,
                    bf16* __restrict__ Kh, bf16* __restrict__ Kl,
                    bf16* __restrict__ Vth, bf16* __restrict__ Vtl,
                    const float* __restrict__ Ct, const float* __restrict__ St) {
    const int n0 = blockIdx.x * BN;
    const int m0 = blockIdx.y * BM;
    const int z  = blockIdx.z;
    const size_t nw = (size_t)DIM * DIM;

    float acc[4][8][4];
    gemm3_core(Ahi, Alo, DIM, Whi + z * nw, Wlo + z * nw, DIM, m0, n0, DIM / BK, acc);

    const int tid = threadIdx.x;
    const int wid = tid >> 5;
    const int lane = tid & 31;
    const int grp = lane >> 2;
    const int tig = lane & 3;
    const int wm = (wid & 1) * 64;
    const int wn = (wid >> 1) * 64;

    if (z != 2) {
        bf16* Ohi = (z == 0) ? Qh : Kh;
        bf16* Olo = (z == 0) ? Ql : Kl;
#pragma unroll
        for (int mt = 0; mt < 4; mt++)
#pragma unroll
            for (int nt = 0; nt < 8; nt++)
#pragma unroll
                for (int h = 0; h < 2; h++) {
                    int row = m0 + wm + mt * 16 + grp + 8 * h;
                    int colE = n0 + wn + nt * 8 + tig * 2;
                    float e = acc[mt][nt][2 * h];
                    float o = acc[mt][nt][2 * h + 1];
                    int s = row & (SEQ - 1);
                    int j = colE >> 1;
                    float cth = Ct[(size_t)s * HALF_D + j];
                    float sth = St[(size_t)s * HALF_D + j];
                    float re = e * cth - o * sth;
                    float ro = e * sth + o * cth;
                    bf16 h1, l1, h2, l2;
                    split_bf16(re, h1, l1);
                    split_bf16(ro, h2, l2);
                    size_t p = (size_t)row * DIM + colE;
                    *(bf162*)(Ohi + p) = bf162{h1, h2};
                    *(bf162*)(Olo + p) = bf162{l1, l2};
                }
    } else {
        // ---- V: stage fp32 tile in smem as [col][row], then coalesced
        //      transposed split stores (16B chunks along seq). ----
        extern __shared__ bf16 smem[];
        float* vbuf = (float*)smem;   // 128 cols x VSTRIDE floats = 68.1 KB <= 80 KB
        // mainloop ended with __syncthreads(); smem free to reuse
#pragma unroll
        for (int mt = 0; mt < 4; mt++)
#pragma unroll
            for (int nt = 0; nt < 8; nt++)
#pragma unroll
                for (int h = 0; h < 2; h++) {
                    int rowL = wm + mt * 16 + grp + 8 * h;
                    int colL = wn + nt * 8 + tig * 2;
                    vbuf[colL * VSTRIDE + rowL]       = acc[mt][nt][2 * h];
                    vbuf[(colL + 1) * VSTRIDE + rowL] = acc[mt][nt][2 * h + 1];
                }
        __syncthreads();

        const int bq = m0 >> 12;          // batch (tiles never straddle)
        const int sbase = m0 & (SEQ - 1);
        const int col = tid;               // 0..127
        const float* srcc = vbuf + col * VSTRIDE;
        size_t gbase = ((size_t)bq * DIM + n0 + col) * SEQ + sbase;
#pragma unroll
        for (int j0 = 0; j0 < 128; j0 += 8) {
            bf16 h8[8], l8[8];
#pragma unroll
            for (int j = 0; j < 8; j++) split_bf16(srcc[j0 + j], h8[j], l8[j]);
            *(uint4*)(Vth + gbase + j0) = *(uint4*)h8;
            *(uint4*)(Vtl + gbase + j0) = *(uint4*)l8;
        }
    }
}

// ============================================================
// Scores+exp: E = exp((Q K^T)/32) masked causal, split bf16 output.
// (No row-max: scores are O(few), exp cannot overflow fp32; softmax
//  is shift-invariant so normalization by the row-sum suffices.)
// grid = (SEQ/BN, SEQ/BM, BATCH)
// ============================================================
__global__ __launch_bounds__(GTH, 2)
void scores_mma_kernel(const bf16* __restrict__ Qhi, const bf16* __restrict__ Qlo,
                       const bf16* __restrict__ Khi, const bf16* __restrict__ Klo,
                       bf16* __restrict__ Pbh, bf16* __restrict__ Pbl) {
    const int n0 = blockIdx.x * BN;
    const int m0 = blockIdx.y * BM;
    if (n0 > m0) return;
    const int b = blockIdx.z;
    const size_t boff = (size_t)b * SEQ * DIM;

    float acc[4][8][4];
    gemm3_core(Qhi + boff, Qlo + boff, DIM, Khi + boff, Klo + boff, DIM,
               m0, n0, DIM / BK, acc);

    const int tid = threadIdx.x;
    const int wid = tid >> 5;
    const int lane = tid & 31;
    const int grp = lane >> 2;
    const int tig = lane & 3;
    const int wm = (wid & 1) * 64;
    const int wn = (wid >> 1) * 64;
    const float scale = 1.0f / 32.0f;

    bf16* Ph = Pbh + (size_t)b * SEQ * SEQ;
    bf16* Pl = Pbl + (size_t)b * SEQ * SEQ;
#pragma unroll
    for (int mt = 0; mt < 4; mt++)
#pragma unroll
        for (int nt = 0; nt < 8; nt++)
#pragma unroll
            for (int h = 0; h < 2; h++) {
                int row = m0 + wm + mt * 16 + grp + 8 * h;
                int col = n0 + wn + nt * 8 + tig * 2;
                float e0 = (col     <= row) ? __expf(acc[mt][nt][2 * h]     * scale) : 0.0f;
                float e1 = (col + 1 <= row) ? __expf(acc[mt][nt][2 * h + 1] * scale) : 0.0f;
                bf16 h0, l0, h1, l1;
                split_bf16(e0, h0, l0);
                split_bf16(e1, h1, l1);
                size_t p = (size_t)row * SEQ + col;
                *(bf162*)(Ph + p) = bf162{h0, h1};
                *(bf162*)(Pl + p) = bf162{l0, l1};
            }
}

// ============================================================
// Deterministic per-row sum of split exp values. Block per row.
// ============================================================
__global__ __launch_bounds__(NTHREADS)
void rowsum_kernel(const bf16* __restrict__ Pbh, const bf16* __restrict__ Pbl,
                   float* __restrict__ rsum) {
    __shared__ float red[NTHREADS / 32];
    const int rowg = blockIdx.x;
    const int b = rowg >> 12;
    const int i = rowg & (SEQ - 1);
    const bf16* ph = Pbh + ((size_t)b * SEQ + i) * SEQ;
    const bf16* pl = Pbl + ((size_t)b * SEQ + i) * SEQ;
    const int bound = (i & ~127) + 128;   // masked zeros cover (i, bound)
    const int tid = threadIdx.x;
    const int lane = tid & 31;
    const int wrp = tid >> 5;

    float sum = 0.0f;
    for (int j = tid * 2; j < bound; j += NTHREADS * 2) {
        bf162 h2 = *(const bf162*)(ph + j);
        bf162 l2 = *(const bf162*)(pl + j);
        sum += __bfloat162float(h2.x) + __bfloat162float(l2.x);
        sum += __bfloat162float(h2.y) + __bfloat162float(l2.y);
    }
#pragma unroll
    for (int o = 16; o > 0; o >>= 1) sum += __shfl_xor_sync(~0u, sum, o);
    if (lane == 0) red[wrp] = sum;
    __syncthreads();
    if (tid == 0) {
        float s = 0.0f;
#pragma unroll
        for (int w = 0; w < NTHREADS / 32; w++) s += red[w];
        rsum[rowg] = s;
    }
}

// ============================================================
// PV: O = (E @ V) / rowsum using Vt (K-major), causal-truncated k-loop.
// grid = (DIM/BN, SEQ/BM, BATCH); m-tiles reversed so heavy tiles go first.
// ============================================================
__global__ __launch_bounds__(GTH, 2)
void pv_mma_kernel(const bf16* __restrict__ Pbh, const bf16* __restrict__ Pbl,
                   const bf16* __restrict__ Vthi, const bf16* __restrict__ Vtlo,
                   const float* __restrict__ rsum, float* __restrict__ O) {
    const int n0 = blockIdx.x * BN;
    const int m0 = (int)(gridDim.y - 1 - blockIdx.y) * BM;   // heavy first
    const int b = blockIdx.z;

    const bf16* Ah = Pbh + (size_t)b * SEQ * SEQ;
    const bf16* Al = Pbl + (size_t)b * SEQ * SEQ;
    const bf16* Bh = Vthi + (size_t)b * DIM * SEQ;
    const bf16* Bl = Vtlo + (size_t)b * DIM * SEQ;

    float acc[4][8][4];
    gemm3_core(Ah, Al, SEQ, Bh, Bl, SEQ, m0, n0, (m0 + BM) / BK, acc);

    const int tid = threadIdx.x;
    const int wid = tid >> 5;
    const int lane = tid & 31;
    const int grp = lane >> 2;
    const int tig = lane & 3;
    const int wm = (wid & 1) * 64;
    const int wn = (wid >> 1) * 64;

#pragma unroll
    for (int mt = 0; mt < 4; mt++)
#pragma unroll
        for (int nt = 0; nt < 8; nt++)
#pragma unroll
            for (int h = 0; h < 2; h++) {
                int row = m0 + wm + mt * 16 + grp + 8 * h;
                int col = n0 + wn + nt * 8 + tig * 2;
                float inv = 1.0f / rsum[(size_t)b * SEQ + row];
                float2 v;
                v.x = acc[mt][nt][2 * h] * inv;
                v.y = acc[mt][nt][2 * h + 1] * inv;
                *(float2*)(O + ((size_t)b * SEQ + row) * DIM + col) = v;
            }
}

// ============================================================
// Launch
// ============================================================
extern "C" void kernel_launch(void* const* d_in, const int* in_sizes, int n_in,
                              void* d_out, int out_size) {
    const float* x  = (const float*)d_in[0];
    const float* Wq = (const float*)d_in[1];
    const float* Wk = (const float*)d_in[2];
    const float* Wv = (const float*)d_in[3];
    float* out = (float*)d_out;

    bf16 *xh, *xl, *Wh, *Wl, *Qh, *Ql, *Kh, *Kl, *Vth, *Vtl, *Pbh, *Pbl;
    float *Rs, *Cp, *Sp;
    cudaGetSymbolAddress((void**)&xh, g_xhi);
    cudaGetSymbolAddress((void**)&xl, g_xlo);
    cudaGetSymbolAddress((void**)&Wh, g_Whi);
    cudaGetSymbolAddress((void**)&Wl, g_Wlo);
    cudaGetSymbolAddress((void**)&Qh, g_Qhi);
    cudaGetSymbolAddress((void**)&Ql, g_Qlo);
    cudaGetSymbolAddress((void**)&Kh, g_Khi);
    cudaGetSymbolAddress((void**)&Kl, g_Klo);
    cudaGetSymbolAddress((void**)&Vth, g_Vthi);
    cudaGetSymbolAddress((void**)&Vtl, g_Vtlo);
    cudaGetSymbolAddress((void**)&Pbh, g_Pbh);
    cudaGetSymbolAddress((void**)&Pbl, g_Pbl);
    cudaGetSymbolAddress((void**)&Rs, g_rsum);
    cudaGetSymbolAddress((void**)&Cp, g_cos);
    cudaGetSymbolAddress((void**)&Sp, g_sin);

    cudaFuncSetAttribute(qkv_mma_kernel,    cudaFuncAttributeMaxDynamicSharedMemorySize, SMEM_BYTES);
    cudaFuncSetAttribute(scores_mma_kernel, cudaFuncAttributeMaxDynamicSharedMemorySize, SMEM_BYTES);
    cudaFuncSetAttribute(pv_mma_kernel,     cudaFuncAttributeMaxDynamicSharedMemorySize, SMEM_BYTES);

    // 1) trig tables
    {
        int total = SEQ * HALF_D;
        trig_table_kernel<<<(total + 255) / 256, 256>>>(Cp, Sp);
    }
    // 2) split x
    {
        int nx = MTOT * DIM;
        split_kernel<<<(nx + 255) / 256, 256>>>(x, xh, xl, nx);
    }
    // 3) split all weights (one launch)
    {
        int n3 = 3 * DIM * DIM;
        split_w3_kernel<<<(n3 + 255) / 256, 256>>>(Wq, Wk, Wv, Wh, Wl);
    }

    // 4) QKV projections (single launch, grid.z selects Q/K/V)
    {
        dim3 grid(DIM / BN, MTOT / BM, 3);   // (8, 128, 3)
        qkv_mma_kernel<<<grid, GTH, SMEM_BYTES>>>(xh, xl, Wh, Wl,
                                                  Qh, Ql, Kh, Kl, Vth, Vtl,
                                                  Cp, Sp);
    }
    // 5) scores + exp + causal mask (split output, no softmax pass)
    {
        dim3 grid(SEQ / BN, SEQ / BM, BATCH);
        scores_mma_kernel<<<grid, GTH, SMEM_BYTES>>>(Qh, Ql, Kh, Kl, Pbh, Pbl);
    }
    // 6) deterministic row sums
    rowsum_kernel<<<BATCH * SEQ, NTHREADS>>>(Pbh, Pbl, Rs);

    // 7) O = (E @ V) / rowsum
    {
        dim3 grid(DIM / BN, SEQ / BM, BATCH);
        pv_mma_kernel<<<grid, GTH, SMEM_BYTES>>>(Pbh, Pbl, Vth, Vtl, Rs, out);
    }
}